// round 12
// baseline (speedup 1.0000x reference)
#include <cuda_runtime.h>
#include <cuda_fp16.h>
#include <cstdint>
#include <cstddef>

#define T_STEPS 500
#define BATCH   128
#define NIN     300
#define EDIM    128
#define CDIM    128
#define UDIM    64
#define FDIM    4
#define G3E     384      // 3*E == 3*C
#define CLIPV   5.0f

// ---------------- scratch (device globals; no runtime allocation) ----------------
__device__ float g_xpf[(size_t)T_STEPS * BATCH * G3E];
__device__ float g_xpb[(size_t)T_STEPS * BATCH * G3E];
__device__ float g_g  [(size_t)T_STEPS * BATCH * 2 * EDIM];
__device__ float g_cp [(size_t)T_STEPS * BATCH * G3E];

// fp16 pre-converted operands: A operands single precision-slice, W operands hi+lo
#define XN4   (T_STEPS * BATCH * NIN / 4)
#define GN4   (T_STEPS * BATCH * 2 * EDIM / 4)
#define WFN4  (G3E * NIN / 4)
#define WCN4  (G3E * (2 * EDIM + NIN) / 4)
__device__ uint2 g_xh[XN4];
__device__ uint2 g_gh[GN4];
__device__ uint2 g_wfh[WFN4], g_wfl[WFN4];
__device__ uint2 g_wbh[WFN4], g_wbl[WFN4];
__device__ uint2 g_wch[WCN4], g_wcl[WCN4];

// ---------------- packed f32x2 helpers ----------------
#define FMA2(acc, a, b) \
    asm volatile("fma.rn.f32x2 %0, %1, %2, %0;" : "+l"(acc) : "l"(a), "l"(b))

__device__ __forceinline__ float sum2(unsigned long long v) {
    float lo, hi;
    asm("mov.b64 {%0, %1}, %2;" : "=f"(lo), "=f"(hi) : "l"(v));
    return lo + hi;
}

__device__ __forceinline__ float sigmf(float x) {
    return __fdividef(1.0f, 1.0f + __expf(-x));
}

// fast tanh via exp identity; err ~1e-6, clamp avoids inf/inf
__device__ __forceinline__ float tanhf_fast(float x) {
    x = fminf(fmaxf(x, -15.f), 15.f);
    float e = __expf(2.0f * x);
    return __fdividef(e - 1.0f, e + 1.0f);
}

// =================================================================================
// fp32 -> fp16 conversions
// =================================================================================
__device__ __forceinline__ uint32_t packh2(__half a, __half b) {
    return ((uint32_t)__half_as_ushort(b) << 16) | __half_as_ushort(a);
}

__global__ __launch_bounds__(256) void conv_half(
    const float4* __restrict__ src, uint2* __restrict__ dst, int n4)
{
    int i = blockIdx.x * 256 + threadIdx.x;
    if (i >= n4) return;
    float4 v = src[i];
    dst[i] = make_uint2(packh2(__float2half_rn(v.x), __float2half_rn(v.y)),
                        packh2(__float2half_rn(v.z), __float2half_rn(v.w)));
}

__global__ __launch_bounds__(256) void conv_half_split(
    const float4* __restrict__ src, uint2* __restrict__ hi, uint2* __restrict__ lo, int n4)
{
    int i = blockIdx.x * 256 + threadIdx.x;
    if (i >= n4) return;
    float4 v = src[i];
    __half h0 = __float2half_rn(v.x);
    __half h1 = __float2half_rn(v.y);
    __half h2 = __float2half_rn(v.z);
    __half h3 = __float2half_rn(v.w);
    hi[i] = make_uint2(packh2(h0, h1), packh2(h2, h3));
    __half l0 = __float2half_rn(v.x - __half2float(h0));
    __half l1 = __float2half_rn(v.y - __half2float(h1));
    __half l2 = __float2half_rn(v.z - __half2float(h2));
    __half l3 = __float2half_rn(v.w - __half2float(h3));
    lo[i] = make_uint2(packh2(l0, l1), packh2(l2, l3));
}

// =================================================================================
// Tensor-core GEMM: fp16 split-2, TWO passes (Ah*Bh + Ah*Bl), fp32 accum.
//   (unchanged — passing, 124us/launch)
// =================================================================================
#define BKT 64
#define TPAD 72
#define TILE_B (128 * TPAD * 2)
#define STAGE_B (3 * TILE_B)
#define SMG_BASE 1024
#define GEMM_SMEM (SMG_BASE + 2 * STAGE_B)   // 111616 -> 2 CTAs/SM

__device__ __forceinline__ uint32_t smem_u32(const void* p) {
    uint32_t a;
    asm("{ .reg .u64 t; cvta.to.shared.u64 t, %1; cvt.u32.u64 %0, t; }" : "=r"(a) : "l"(p));
    return a;
}

__device__ __forceinline__ void ldm_x4(uint32_t* r, uint32_t addr) {
    asm volatile("ldmatrix.sync.aligned.m8n8.x4.shared.b16 {%0,%1,%2,%3}, [%4];"
                 : "=r"(r[0]), "=r"(r[1]), "=r"(r[2]), "=r"(r[3]) : "r"(addr));
}

__device__ __forceinline__ void mma_fp16(float* d, const uint32_t* a, uint32_t b0, uint32_t b1) {
    asm volatile(
        "mma.sync.aligned.m16n8k16.row.col.f32.f16.f16.f32 "
        "{%0,%1,%2,%3}, {%4,%5,%6,%7}, {%8,%9}, {%0,%1,%2,%3};"
        : "+f"(d[0]), "+f"(d[1]), "+f"(d[2]), "+f"(d[3])
        : "r"(a[0]), "r"(a[1]), "r"(a[2]), "r"(a[3]), "r"(b0), "r"(b1));
}

__device__ __forceinline__ void cp_tile(
    const __half* __restrict__ src, int stride, int row0,
    int kbase, int kmax, uint32_t smDst, int tid)
{
    #pragma unroll
    for (int i = 0; i < 8; i++) {
        int idx = i * 256 + tid;
        int r = idx >> 4, c4 = idx & 15;
        int kg = kbase + c4 * 4;
        int sz = (kg < kmax) ? 8 : 0;
        int kgc = (kg < kmax) ? kg : 0;
        size_t off = (size_t)(row0 + r) * stride + kgc;
        uint32_t so = (uint32_t)(r * TPAD + c4 * 4) * 2;
        asm volatile("cp.async.ca.shared.global [%0], [%1], 8, %2;"
                     :: "r"(smDst + so), "l"(src + off), "r"(sz));
    }
}

__global__ __launch_bounds__(256, 2) void gemm_mma(
    const uint2* Ah0u, int K0, const uint2* Ah1u, int K1,
    const uint2* Whiu, const uint2* Wlou,
    const float* __restrict__ bias, float* __restrict__ C, int reverse)
{
    extern __shared__ char sm[];
    const __half* Ah0 = (const __half*)Ah0u;
    const __half* Ah1 = (const __half*)Ah1u;
    const __half* Whi = (const __half*)Whiu;
    const __half* Wlo = (const __half*)Wlou;

    const int tid  = threadIdx.x;
    const int warp = tid >> 5, lane = tid & 31;
    const int tb = blockIdx.x;
    const int n0 = blockIdx.y * 128;
    const int Ktot = K0 + K1;
    const int nkt = (Ktot + BKT - 1) / BKT;

    const int m0w = (warp >> 1) * 32;
    const int n0w = (warp & 1) * 64;
    const int laneRow  = lane & 15;
    const int laneHalf = lane >> 4;

    float* biass = (float*)sm;
    if (tid < 128) biass[tid] = bias[n0 + tid];

    const int arow0 = (reverse ? (T_STEPS - 1 - tb) : tb) * BATCH;
    const int crow0 = tb * BATCH;

    const uint32_t smBase = smem_u32(sm + SMG_BASE);

    float acc[2][8][4];
    #pragma unroll
    for (int mi = 0; mi < 2; mi++)
        #pragma unroll
        for (int nf = 0; nf < 8; nf++)
            #pragma unroll
            for (int q = 0; q < 4; q++) acc[mi][nf][q] = 0.f;

    auto issue_tile = [&](int kt) {
        const int k0 = kt * BKT;
        const uint32_t stg = smBase + (uint32_t)(kt & 1) * STAGE_B;
        if (k0 < K0)
            cp_tile(Ah0, K0, arow0, k0, K0, stg, tid);
        else
            cp_tile(Ah1, K1, arow0, k0 - K0, K1, stg, tid);
        cp_tile(Whi, Ktot, n0, k0, Ktot, stg + TILE_B, tid);
        cp_tile(Wlo, Ktot, n0, k0, Ktot, stg + 2 * TILE_B, tid);
    };

    issue_tile(0);
    asm volatile("cp.async.commit_group;" ::: "memory");

    for (int kt = 0; kt < nkt; kt++) {
        if (kt + 1 < nkt) issue_tile(kt + 1);
        asm volatile("cp.async.commit_group;" ::: "memory");
        asm volatile("cp.async.wait_group 1;" ::: "memory");
        __syncthreads();

        const uint32_t stg = smBase + (uint32_t)(kt & 1) * STAGE_B;
        const uint32_t sbA   = stg;
        const uint32_t sbBHI = stg + TILE_B;
        const uint32_t sbBLO = stg + 2 * TILE_B;

        #pragma unroll
        for (int ks = 0; ks < 4; ks++) {
            const uint32_t colb = (uint32_t)(ks * 16 + laneHalf * 8) * 2;

            uint32_t ah[2][4];
            #pragma unroll
            for (int mi = 0; mi < 2; mi++) {
                uint32_t ro = (uint32_t)(m0w + mi * 16 + laneRow) * (TPAD * 2) + colb;
                ldm_x4(ah[mi], sbA + ro);
            }
            uint32_t bh[8][2], bl[8][2];
            #pragma unroll
            for (int ni = 0; ni < 4; ni++) {
                uint32_t ro = (uint32_t)(n0w + ni * 16 + laneRow) * (TPAD * 2) + colb;
                uint32_t rb[4];
                ldm_x4(rb, sbBHI + ro);
                bh[2 * ni][0] = rb[0]; bh[2 * ni][1] = rb[2];
                bh[2 * ni + 1][0] = rb[1]; bh[2 * ni + 1][1] = rb[3];
                ldm_x4(rb, sbBLO + ro);
                bl[2 * ni][0] = rb[0]; bl[2 * ni][1] = rb[2];
                bl[2 * ni + 1][0] = rb[1]; bl[2 * ni + 1][1] = rb[3];
            }
            #pragma unroll
            for (int mi = 0; mi < 2; mi++)
                #pragma unroll
                for (int nf = 0; nf < 8; nf++)
                    mma_fp16(acc[mi][nf], ah[mi], bh[nf][0], bh[nf][1]);
            #pragma unroll
            for (int mi = 0; mi < 2; mi++)
                #pragma unroll
                for (int nf = 0; nf < 8; nf++)
                    mma_fp16(acc[mi][nf], ah[mi], bl[nf][0], bl[nf][1]);
        }
        __syncthreads();
    }

    float* stage = (float*)(sm + SMG_BASE);
    {
        const int g = lane >> 2, t4 = lane & 3;
        #pragma unroll
        for (int mi = 0; mi < 2; mi++)
            #pragma unroll
            for (int nf = 0; nf < 8; nf++) {
                int col = n0w + nf * 8 + 2 * t4;
                float* p0 = &stage[(m0w + mi * 16 + g) * 132 + col];
                float* p1 = &stage[(m0w + mi * 16 + g + 8) * 132 + col];
                p0[0] = acc[mi][nf][0]; p0[1] = acc[mi][nf][1];
                p1[0] = acc[mi][nf][2]; p1[1] = acc[mi][nf][3];
            }
    }
    __syncthreads();
    {
        const int col = tid & 127;
        const float bcol = biass[col];
        #pragma unroll 4
        for (int it = 0; it < 64; it++) {
            int r = it * 2 + (tid >> 7);
            C[(size_t)(crow0 + r) * G3E + n0 + col] = stage[r * 132 + col] + bcol;
        }
    }
}

// ---------------------------------------------------------------------------------
// Encoder bidirectional GRU scan — TWO batch rows per CTA (shared weight regs).
// grid = 128 CTAs: blk>>6 = dir, blk&63 = batch pair. 384 threads, 1 wave.
// ---------------------------------------------------------------------------------
__global__ __launch_bounds__(384, 1) void enc_scan(
    const float* __restrict__ Whh_f, const float* __restrict__ bhh_f,
    const float* __restrict__ Whh_b, const float* __restrict__ bhh_b,
    const float* __restrict__ enc_init)
{
    const int j = threadIdx.x;
    const int dir = blockIdx.x >> 6;
    const int bp  = blockIdx.x & 63;
    const int b0 = bp * 2;
    const float* Whh = dir ? Whh_b : Whh_f;
    const float* bhh = dir ? bhh_b : bhh_f;
    const float* xp = dir ? g_xpb : g_xpf;

    unsigned long long w2[64];
    {
        const unsigned long long* wr = (const unsigned long long*)(Whh + j * 128);
        #pragma unroll
        for (int k = 0; k < 64; k++) w2[k] = wr[k];
    }
    const float bh = bhh[j];

    __shared__ __align__(16) float h0_s[128];
    __shared__ __align__(16) float h1_s[128];
    __shared__ float hh0_s[384];
    __shared__ float hh1_s[384];
    if (j < 128) {
        float hi = enc_init[dir * 128 + j];
        h0_s[j] = hi; h1_s[j] = hi;
    }
    __syncthreads();

    const ulonglong2* h0v = (const ulonglong2*)h0_s;
    const ulonglong2* h1v = (const ulonglong2*)h1_s;

    // per-thread input prefetch: threads [0,128) hold row b0, [128,256) row b1
    const int jj = j & 127;
    const int myb = b0 + ((j >> 7) & 1);       // b0 for j<128, b1 for 128..255
    float pr = 0.f, pz = 0.f, pn = 0.f;
    if (j < 256) {
        const float* xr = xp + (size_t)myb * G3E;
        pr = xr[jj]; pz = xr[128 + jj]; pn = xr[256 + jj];
    }

    for (int t = 0; t < T_STEPS; t++) {
        float npr = 0.f, npz = 0.f, npn = 0.f;
        if (t + 1 < T_STEPS && j < 256) {
            const float* xr = xp + ((size_t)(t + 1) * BATCH + myb) * G3E;
            npr = xr[jj]; npz = xr[128 + jj]; npn = xr[256 + jj];
        }

        // dots for BOTH rows with shared weights: 2 chains each, full unroll
        unsigned long long c00 = 0ull, c01 = 0ull, c10 = 0ull, c11 = 0ull;
        #pragma unroll
        for (int kk = 0; kk < 32; kk++) {
            ulonglong2 a0 = h0v[kk];
            ulonglong2 a1 = h1v[kk];
            FMA2(c00, w2[2 * kk + 0], a0.x);
            FMA2(c01, w2[2 * kk + 1], a0.y);
            FMA2(c10, w2[2 * kk + 0], a1.x);
            FMA2(c11, w2[2 * kk + 1], a1.y);
        }
        hh0_s[j] = bh + (sum2(c00) + sum2(c01));
        hh1_s[j] = bh + (sum2(c10) + sum2(c11));
        __syncthreads();

        if (j < 256) {
            const float* hhs = (j < 128) ? hh0_s : hh1_s;
            float* hs = (j < 128) ? h0_s : h1_s;
            float r = sigmf(pr + hhs[jj]);
            float z = sigmf(pz + hhs[128 + jj]);
            float n = tanhf_fast(pn + r * hhs[256 + jj]);
            float h = (1.f - z) * n + z * hs[jj];
            hs[jj] = h;
            float gc = fminf(fmaxf(h, -CLIPV), CLIPV);
            int tt = dir ? (T_STEPS - 1 - t) : t;
            g_g[((size_t)tt * BATCH + myb) * (2 * EDIM) + dir * EDIM + jj] = gc;
        }
        __syncthreads();
        pr = npr; pz = npz; pn = npn;
    }
}

// ---------------------------------------------------------------------------------
// Controller scan — merged mu/lv (3 barriers/step), full-unroll chains.
// ---------------------------------------------------------------------------------
#define CTRL_SMEM_FLOATS 40832
#define CTRL_SMEM_BYTES  (CTRL_SMEM_FLOATS * 4)

__global__ __launch_bounds__(384, 1) void ctrl_scan(
    const float* __restrict__ factors, const float* __restrict__ eps,
    const float* __restrict__ Whh, const float* __restrict__ bhh,
    const float* __restrict__ cinit,
    const float* __restrict__ W_mu, const float* __restrict__ b_mu,
    const float* __restrict__ W_lv, const float* __restrict__ b_lv,
    const float* __restrict__ W_spk, const float* __restrict__ b_spk,
    const float* __restrict__ gain_p, const float* __restrict__ biasp_p,
    const float* __restrict__ logtau_p,
    float* __restrict__ out)
{
    extern __shared__ __align__(16) float smf[];
    float* wml  = smf;            // 128 x 132 (rows 0..63 = W_mu, 64..127 = W_lv)
    float* wspk = smf + 16896;    // 300 x 76
    float* h_s  = smf + 39696;    // 128
    float* hh_s = smf + 39824;    // 384
    float* gen  = smf + 40336;    // 68 (16B aligned)
    float* bml  = smf + 40404;    // 128
    float* bsp  = smf + 40532;    // 300

    const int j = threadIdx.x;
    const int b = blockIdx.x;

    unsigned long long w2[64];
    {
        const unsigned long long* wr = (const unsigned long long*)(Whh + j * 128);
        #pragma unroll
        for (int k = 0; k < 64; k++) w2[k] = wr[k];
    }
    const float bh = bhh[j];

    for (int idx = j; idx < 128 * 128; idx += 384) {
        int r = idx >> 7, k = idx & 127;
        wml[r * 132 + k] = (r < 64) ? W_mu[r * 128 + k] : W_lv[(r - 64) * 128 + k];
    }
    for (int idx = j; idx < 300 * 68; idx += 384) {
        int r = idx / 68, k = idx - r * 68;
        wspk[r * 76 + k] = W_spk[idx];
    }
    if (j < 128) { bml[j] = (j < 64) ? b_mu[j] : b_lv[j - 64]; h_s[j] = cinit[j]; }
    if (j < 300) bsp[j] = b_spk[j];

    const float gain  = gain_p[0];
    const float biasp = biasp_p[0];
    const float decay = 1.f - expf(-logtau_p[0]);
    float cal = 0.f;
    __syncthreads();

    const ulonglong2* h2v = (const ulonglong2*)h_s;
    const ulonglong2* g2v = (const ulonglong2*)gen;

    float pr = 0.f, pz = 0.f, pn = 0.f, ev = 0.f, fv = 0.f;
    {
        const float* cpr = g_cp + (size_t)b * G3E;
        if (j < 128) { pr = cpr[j]; pz = cpr[128 + j]; pn = cpr[256 + j]; }
        if (j < UDIM) ev = eps[(size_t)b * UDIM + j];
        else if (j < UDIM + FDIM) fv = factors[(size_t)b * FDIM + (j - UDIM)];
    }

    for (int t = 0; t < T_STEPS; t++) {
        size_t row = (size_t)t * BATCH + b;

        float npr = 0.f, npz = 0.f, npn = 0.f, nev = 0.f, nfv = 0.f;
        if (t + 1 < T_STEPS) {
            size_t nrow = row + BATCH;
            const float* cpr = g_cp + nrow * G3E;
            if (j < 128) { npr = cpr[j]; npz = cpr[128 + j]; npn = cpr[256 + j]; }
            if (j < UDIM) nev = eps[nrow * UDIM + j];
            else if (j < UDIM + FDIM) nfv = factors[nrow * FDIM + (j - UDIM)];
        }

        // phase 1: hh = Whh @ h + bhh (4-chain, full unroll)
        unsigned long long c0 = 0ull, c1 = 0ull, c2 = 0ull, c3 = 0ull;
        #pragma unroll
        for (int kk = 0; kk < 16; kk++) {
            ulonglong2 ha = h2v[2 * kk];
            ulonglong2 hb = h2v[2 * kk + 1];
            FMA2(c0, w2[4 * kk + 0], ha.x);
            FMA2(c1, w2[4 * kk + 1], ha.y);
            FMA2(c2, w2[4 * kk + 2], hb.x);
            FMA2(c3, w2[4 * kk + 3], hb.y);
        }
        hh_s[j] = bh + ((sum2(c0) + sum2(c1)) + (sum2(c2) + sum2(c3)));
        __syncthreads();

        // phase 2: gates, clip
        if (j < 128) {
            float r = sigmf(pr + hh_s[j]);
            float z = sigmf(pz + hh_s[128 + j]);
            float n = tanhf_fast(pn + r * hh_s[256 + j]);
            float h = (1.f - z) * n + z * h_s[j];
            h = fminf(fmaxf(h, -CLIPV), CLIPV);
            h_s[j] = h;
        }
        __syncthreads();

        // phase 3: thread j<64 computes BOTH mu_j and lv_j, writes gen[j] directly
        if (j < UDIM) {
            unsigned long long m0 = 0ull, m1 = 0ull, l0 = 0ull, l1 = 0ull;
            const ulonglong2* wmu = (const ulonglong2*)&wml[j * 132];
            const ulonglong2* wlv = (const ulonglong2*)&wml[(UDIM + j) * 132];
            #pragma unroll
            for (int kk = 0; kk < 32; kk++) {
                ulonglong2 hv = h2v[kk];
                ulonglong2 wm = wmu[kk];
                ulonglong2 wl = wlv[kk];
                FMA2(m0, wm.x, hv.x);
                FMA2(m1, wm.y, hv.y);
                FMA2(l0, wl.x, hv.x);
                FMA2(l1, wl.y, hv.y);
            }
            float mu = bml[j] + (sum2(m0) + sum2(m1));
            float lv = bml[UDIM + j] + (sum2(l0) + sum2(l1));
            gen[j] = mu + __expf(0.5f * lv) * ev;
        } else if (j < UDIM + FDIM) {
            gen[j] = fv;
        }
        __syncthreads();

        // phase 4: spike + calcium
        if (j < NIN) {
            unsigned long long s01 = 0ull, s23 = 0ull;
            const ulonglong2* wr2 = (const ulonglong2*)&wspk[j * 76];
            #pragma unroll
            for (int kk = 0; kk < 17; kk++) {
                ulonglong2 wv = wr2[kk];
                ulonglong2 gv = g2v[kk];
                FMA2(s01, wv.x, gv.x);
                FMA2(s23, wv.y, gv.y);
            }
            float logit = bsp[j] + (sum2(s01) + sum2(s23));
            float spike = fmaxf(__expf(logit) - 1.f, 0.f);
            cal = cal * decay + gain * spike + biasp;
            out[row * NIN + j] = cal;
        }
        pr = npr; pz = npz; pn = npn; ev = nev; fv = nfv;
    }
}

// ---------------------------------------------------------------------------------
extern "C" void kernel_launch(void* const* d_in, const int* in_sizes, int n_in,
                              void* d_out, int out_size)
{
    (void)in_sizes; (void)n_in; (void)out_size;
    const float* x       = (const float*)d_in[0];
    const float* factors = (const float*)d_in[1];
    const float* eps     = (const float*)d_in[2];
    const float* eWihf   = (const float*)d_in[3];
    const float* eWhhf   = (const float*)d_in[4];
    const float* ebihf   = (const float*)d_in[5];
    const float* ebhhf   = (const float*)d_in[6];
    const float* eWihb   = (const float*)d_in[7];
    const float* eWhhb   = (const float*)d_in[8];
    const float* ebihb   = (const float*)d_in[9];
    const float* ebhhb   = (const float*)d_in[10];
    const float* einit   = (const float*)d_in[11];
    const float* cWih    = (const float*)d_in[12];
    const float* cWhh    = (const float*)d_in[13];
    const float* cbih    = (const float*)d_in[14];
    const float* cbhh    = (const float*)d_in[15];
    const float* cinit   = (const float*)d_in[16];
    const float* Wmu     = (const float*)d_in[17];
    const float* bmu     = (const float*)d_in[18];
    const float* Wlv     = (const float*)d_in[19];
    const float* blv     = (const float*)d_in[20];
    const float* Wspk    = (const float*)d_in[21];
    const float* bspk    = (const float*)d_in[22];
    const float* gain    = (const float*)d_in[23];
    const float* bp      = (const float*)d_in[24];
    const float* ltau    = (const float*)d_in[25];
    float* out = (float*)d_out;

    float *xpf, *xpb, *gg, *cp;
    cudaGetSymbolAddress((void**)&xpf, g_xpf);
    cudaGetSymbolAddress((void**)&xpb, g_xpb);
    cudaGetSymbolAddress((void**)&gg,  g_g);
    cudaGetSymbolAddress((void**)&cp,  g_cp);

    uint2 *xh, *gh, *wfh, *wfl, *wbh, *wbl, *wch, *wcl;
    cudaGetSymbolAddress((void**)&xh, g_xh);
    cudaGetSymbolAddress((void**)&gh, g_gh);
    cudaGetSymbolAddress((void**)&wfh, g_wfh); cudaGetSymbolAddress((void**)&wfl, g_wfl);
    cudaGetSymbolAddress((void**)&wbh, g_wbh); cudaGetSymbolAddress((void**)&wbl, g_wbl);
    cudaGetSymbolAddress((void**)&wch, g_wch); cudaGetSymbolAddress((void**)&wcl, g_wcl);

    cudaFuncSetAttribute(gemm_mma, cudaFuncAttributeMaxDynamicSharedMemorySize, GEMM_SMEM);
    cudaFuncSetAttribute(ctrl_scan, cudaFuncAttributeMaxDynamicSharedMemorySize, CTRL_SMEM_BYTES);

    dim3 gemm_grid(T_STEPS, G3E / 128);

    conv_half<<<(XN4 + 255) / 256, 256>>>((const float4*)x, xh, XN4);
    conv_half_split<<<(WFN4 + 255) / 256, 256>>>((const float4*)eWihf, wfh, wfl, WFN4);
    conv_half_split<<<(WFN4 + 255) / 256, 256>>>((const float4*)eWihb, wbh, wbl, WFN4);
    gemm_mma<<<gemm_grid, 256, GEMM_SMEM>>>(xh, NIN, nullptr, 0, wfh, wfl, ebihf, xpf, 0);
    conv_half_split<<<(WCN4 + 255) / 256, 256>>>((const float4*)cWih, wch, wcl, WCN4);
    gemm_mma<<<gemm_grid, 256, GEMM_SMEM>>>(xh, NIN, nullptr, 0, wbh, wbl, ebihb, xpb, 1);

    // bidirectional encoder scan -> g (128 CTAs, 2 batch rows each, 1 wave)
    enc_scan<<<128, 384>>>(eWhhf, ebhhf, eWhhb, ebhhb, einit);

    // convert g, then cp = [g, x] @ ctrl_Wih^T + b
    conv_half<<<(GN4 + 255) / 256, 256>>>((const float4*)gg, gh, GN4);
    gemm_mma<<<gemm_grid, 256, GEMM_SMEM>>>(gh, 2 * EDIM, xh, NIN, wch, wcl, cbih, cp, 0);

    // controller scan -> calcium (d_out)
    ctrl_scan<<<128, 384, CTRL_SMEM_BYTES>>>(factors, eps, cWhh, cbhh, cinit,
                                             Wmu, bmu, Wlv, blv, Wspk, bspk,
                                             gain, bp, ltau, out);
}

// round 13
// speedup vs baseline: 1.1120x; 1.1120x over previous
#include <cuda_runtime.h>
#include <cuda_fp16.h>
#include <cstdint>
#include <cstddef>

#define T_STEPS 500
#define BATCH   128
#define NIN     300
#define EDIM    128
#define CDIM    128
#define UDIM    64
#define FDIM    4
#define G3E     384      // 3*E == 3*C
#define CLIPV   5.0f

// ---------------- scratch (device globals; no runtime allocation) ----------------
__device__ float g_xpf[(size_t)T_STEPS * BATCH * G3E];
__device__ float g_xpb[(size_t)T_STEPS * BATCH * G3E];
__device__ float g_g  [(size_t)T_STEPS * BATCH * 2 * EDIM];
__device__ float g_cp [(size_t)T_STEPS * BATCH * G3E];

// fp16 pre-converted operands: A operands single precision-slice, W operands hi+lo
#define XN4   (T_STEPS * BATCH * NIN / 4)
#define GN4   (T_STEPS * BATCH * 2 * EDIM / 4)
#define WFN4  (G3E * NIN / 4)
#define WCN4  (G3E * (2 * EDIM + NIN) / 4)
__device__ uint2 g_xh[XN4];
__device__ uint2 g_gh[GN4];
__device__ uint2 g_wfh[WFN4], g_wfl[WFN4];
__device__ uint2 g_wbh[WFN4], g_wbl[WFN4];
__device__ uint2 g_wch[WCN4], g_wcl[WCN4];

// ---------------- packed f32x2 helpers ----------------
#define FMA2(acc, a, b) \
    asm volatile("fma.rn.f32x2 %0, %1, %2, %0;" : "+l"(acc) : "l"(a), "l"(b))

__device__ __forceinline__ float sum2(unsigned long long v) {
    float lo, hi;
    asm("mov.b64 {%0, %1}, %2;" : "=f"(lo), "=f"(hi) : "l"(v));
    return lo + hi;
}

__device__ __forceinline__ float sigmf(float x) {
    return __fdividef(1.0f, 1.0f + __expf(-x));
}

// fast tanh via exp identity; err ~1e-6, clamp avoids inf/inf
__device__ __forceinline__ float tanhf_fast(float x) {
    x = fminf(fmaxf(x, -15.f), 15.f);
    float e = __expf(2.0f * x);
    return __fdividef(e - 1.0f, e + 1.0f);
}

// =================================================================================
// fp32 -> fp16 conversions
// =================================================================================
__device__ __forceinline__ uint32_t packh2(__half a, __half b) {
    return ((uint32_t)__half_as_ushort(b) << 16) | __half_as_ushort(a);
}

__global__ __launch_bounds__(256) void conv_half(
    const float4* __restrict__ src, uint2* __restrict__ dst, int n4)
{
    int i = blockIdx.x * 256 + threadIdx.x;
    if (i >= n4) return;
    float4 v = src[i];
    dst[i] = make_uint2(packh2(__float2half_rn(v.x), __float2half_rn(v.y)),
                        packh2(__float2half_rn(v.z), __float2half_rn(v.w)));
}

__global__ __launch_bounds__(256) void conv_half_split(
    const float4* __restrict__ src, uint2* __restrict__ hi, uint2* __restrict__ lo, int n4)
{
    int i = blockIdx.x * 256 + threadIdx.x;
    if (i >= n4) return;
    float4 v = src[i];
    __half h0 = __float2half_rn(v.x);
    __half h1 = __float2half_rn(v.y);
    __half h2 = __float2half_rn(v.z);
    __half h3 = __float2half_rn(v.w);
    hi[i] = make_uint2(packh2(h0, h1), packh2(h2, h3));
    __half l0 = __float2half_rn(v.x - __half2float(h0));
    __half l1 = __float2half_rn(v.y - __half2float(h1));
    __half l2 = __float2half_rn(v.z - __half2float(h2));
    __half l3 = __float2half_rn(v.w - __half2float(h3));
    lo[i] = make_uint2(packh2(l0, l1), packh2(l2, l3));
}

// =================================================================================
// Tensor-core GEMM: fp16 split-2, TWO passes (Ah*Bh + Ah*Bl), fp32 accum.
//   (unchanged — passing, 124us/launch)
// =================================================================================
#define BKT 64
#define TPAD 72
#define TILE_B (128 * TPAD * 2)
#define STAGE_B (3 * TILE_B)
#define SMG_BASE 1024
#define GEMM_SMEM (SMG_BASE + 2 * STAGE_B)   // 111616 -> 2 CTAs/SM

__device__ __forceinline__ uint32_t smem_u32(const void* p) {
    uint32_t a;
    asm("{ .reg .u64 t; cvta.to.shared.u64 t, %1; cvt.u32.u64 %0, t; }" : "=r"(a) : "l"(p));
    return a;
}

__device__ __forceinline__ void ldm_x4(uint32_t* r, uint32_t addr) {
    asm volatile("ldmatrix.sync.aligned.m8n8.x4.shared.b16 {%0,%1,%2,%3}, [%4];"
                 : "=r"(r[0]), "=r"(r[1]), "=r"(r[2]), "=r"(r[3]) : "r"(addr));
}

__device__ __forceinline__ void mma_fp16(float* d, const uint32_t* a, uint32_t b0, uint32_t b1) {
    asm volatile(
        "mma.sync.aligned.m16n8k16.row.col.f32.f16.f16.f32 "
        "{%0,%1,%2,%3}, {%4,%5,%6,%7}, {%8,%9}, {%0,%1,%2,%3};"
        : "+f"(d[0]), "+f"(d[1]), "+f"(d[2]), "+f"(d[3])
        : "r"(a[0]), "r"(a[1]), "r"(a[2]), "r"(a[3]), "r"(b0), "r"(b1));
}

__device__ __forceinline__ void cp_tile(
    const __half* __restrict__ src, int stride, int row0,
    int kbase, int kmax, uint32_t smDst, int tid)
{
    #pragma unroll
    for (int i = 0; i < 8; i++) {
        int idx = i * 256 + tid;
        int r = idx >> 4, c4 = idx & 15;
        int kg = kbase + c4 * 4;
        int sz = (kg < kmax) ? 8 : 0;
        int kgc = (kg < kmax) ? kg : 0;
        size_t off = (size_t)(row0 + r) * stride + kgc;
        uint32_t so = (uint32_t)(r * TPAD + c4 * 4) * 2;
        asm volatile("cp.async.ca.shared.global [%0], [%1], 8, %2;"
                     :: "r"(smDst + so), "l"(src + off), "r"(sz));
    }
}

__global__ __launch_bounds__(256, 2) void gemm_mma(
    const uint2* Ah0u, int K0, const uint2* Ah1u, int K1,
    const uint2* Whiu, const uint2* Wlou,
    const float* __restrict__ bias, float* __restrict__ C, int reverse)
{
    extern __shared__ char sm[];
    const __half* Ah0 = (const __half*)Ah0u;
    const __half* Ah1 = (const __half*)Ah1u;
    const __half* Whi = (const __half*)Whiu;
    const __half* Wlo = (const __half*)Wlou;

    const int tid  = threadIdx.x;
    const int warp = tid >> 5, lane = tid & 31;
    const int tb = blockIdx.x;
    const int n0 = blockIdx.y * 128;
    const int Ktot = K0 + K1;
    const int nkt = (Ktot + BKT - 1) / BKT;

    const int m0w = (warp >> 1) * 32;
    const int n0w = (warp & 1) * 64;
    const int laneRow  = lane & 15;
    const int laneHalf = lane >> 4;

    float* biass = (float*)sm;
    if (tid < 128) biass[tid] = bias[n0 + tid];

    const int arow0 = (reverse ? (T_STEPS - 1 - tb) : tb) * BATCH;
    const int crow0 = tb * BATCH;

    const uint32_t smBase = smem_u32(sm + SMG_BASE);

    float acc[2][8][4];
    #pragma unroll
    for (int mi = 0; mi < 2; mi++)
        #pragma unroll
        for (int nf = 0; nf < 8; nf++)
            #pragma unroll
            for (int q = 0; q < 4; q++) acc[mi][nf][q] = 0.f;

    auto issue_tile = [&](int kt) {
        const int k0 = kt * BKT;
        const uint32_t stg = smBase + (uint32_t)(kt & 1) * STAGE_B;
        if (k0 < K0)
            cp_tile(Ah0, K0, arow0, k0, K0, stg, tid);
        else
            cp_tile(Ah1, K1, arow0, k0 - K0, K1, stg, tid);
        cp_tile(Whi, Ktot, n0, k0, Ktot, stg + TILE_B, tid);
        cp_tile(Wlo, Ktot, n0, k0, Ktot, stg + 2 * TILE_B, tid);
    };

    issue_tile(0);
    asm volatile("cp.async.commit_group;" ::: "memory");

    for (int kt = 0; kt < nkt; kt++) {
        if (kt + 1 < nkt) issue_tile(kt + 1);
        asm volatile("cp.async.commit_group;" ::: "memory");
        asm volatile("cp.async.wait_group 1;" ::: "memory");
        __syncthreads();

        const uint32_t stg = smBase + (uint32_t)(kt & 1) * STAGE_B;
        const uint32_t sbA   = stg;
        const uint32_t sbBHI = stg + TILE_B;
        const uint32_t sbBLO = stg + 2 * TILE_B;

        #pragma unroll
        for (int ks = 0; ks < 4; ks++) {
            const uint32_t colb = (uint32_t)(ks * 16 + laneHalf * 8) * 2;

            uint32_t ah[2][4];
            #pragma unroll
            for (int mi = 0; mi < 2; mi++) {
                uint32_t ro = (uint32_t)(m0w + mi * 16 + laneRow) * (TPAD * 2) + colb;
                ldm_x4(ah[mi], sbA + ro);
            }
            uint32_t bh[8][2], bl[8][2];
            #pragma unroll
            for (int ni = 0; ni < 4; ni++) {
                uint32_t ro = (uint32_t)(n0w + ni * 16 + laneRow) * (TPAD * 2) + colb;
                uint32_t rb[4];
                ldm_x4(rb, sbBHI + ro);
                bh[2 * ni][0] = rb[0]; bh[2 * ni][1] = rb[2];
                bh[2 * ni + 1][0] = rb[1]; bh[2 * ni + 1][1] = rb[3];
                ldm_x4(rb, sbBLO + ro);
                bl[2 * ni][0] = rb[0]; bl[2 * ni][1] = rb[2];
                bl[2 * ni + 1][0] = rb[1]; bl[2 * ni + 1][1] = rb[3];
            }
            #pragma unroll
            for (int mi = 0; mi < 2; mi++)
                #pragma unroll
                for (int nf = 0; nf < 8; nf++)
                    mma_fp16(acc[mi][nf], ah[mi], bh[nf][0], bh[nf][1]);
            #pragma unroll
            for (int mi = 0; mi < 2; mi++)
                #pragma unroll
                for (int nf = 0; nf < 8; nf++)
                    mma_fp16(acc[mi][nf], ah[mi], bl[nf][0], bl[nf][1]);
        }
        __syncthreads();
    }

    float* stage = (float*)(sm + SMG_BASE);
    {
        const int g = lane >> 2, t4 = lane & 3;
        #pragma unroll
        for (int mi = 0; mi < 2; mi++)
            #pragma unroll
            for (int nf = 0; nf < 8; nf++) {
                int col = n0w + nf * 8 + 2 * t4;
                float* p0 = &stage[(m0w + mi * 16 + g) * 132 + col];
                float* p1 = &stage[(m0w + mi * 16 + g + 8) * 132 + col];
                p0[0] = acc[mi][nf][0]; p0[1] = acc[mi][nf][1];
                p1[0] = acc[mi][nf][2]; p1[1] = acc[mi][nf][3];
            }
    }
    __syncthreads();
    {
        const int col = tid & 127;
        const float bcol = biass[col];
        #pragma unroll 4
        for (int it = 0; it < 64; it++) {
            int r = it * 2 + (tid >> 7);
            C[(size_t)(crow0 + r) * G3E + n0 + col] = stage[r * 132 + col] + bcol;
        }
    }
}

// ---------------------------------------------------------------------------------
// Encoder bidirectional GRU scan — EXACT R11 version (256 CTAs, 1 row/CTA).
// ---------------------------------------------------------------------------------
__global__ __launch_bounds__(384, 1) void enc_scan(
    const float* __restrict__ Whh_f, const float* __restrict__ bhh_f,
    const float* __restrict__ Whh_b, const float* __restrict__ bhh_b,
    const float* __restrict__ enc_init)
{
    const int j = threadIdx.x;
    const int dir = blockIdx.x >> 7;
    const int b = blockIdx.x & 127;
    const float* Whh = dir ? Whh_b : Whh_f;
    const float* bhh = dir ? bhh_b : bhh_f;
    const float* xp = dir ? g_xpb : g_xpf;

    unsigned long long w2[64];
    {
        const unsigned long long* wr = (const unsigned long long*)(Whh + j * 128);
        #pragma unroll
        for (int k = 0; k < 64; k++) w2[k] = wr[k];
    }
    const float bh = bhh[j];

    __shared__ __align__(16) float h_s[128];
    __shared__ float hh_s[384];
    if (j < 128) h_s[j] = enc_init[dir * 128 + j];
    __syncthreads();

    const ulonglong2* h2v = (const ulonglong2*)h_s;

    float pr = 0.f, pz = 0.f, pn = 0.f;
    if (j < 128) {
        const float* xr = xp + (size_t)b * G3E;
        pr = xr[j]; pz = xr[128 + j]; pn = xr[256 + j];
    }

    for (int t = 0; t < T_STEPS; t++) {
        float npr = 0.f, npz = 0.f, npn = 0.f;
        if (t + 1 < T_STEPS && j < 128) {
            const float* xr = xp + ((size_t)(t + 1) * BATCH + b) * G3E;
            npr = xr[j]; npz = xr[128 + j]; npn = xr[256 + j];
        }

        unsigned long long c0 = 0ull, c1 = 0ull, c2 = 0ull, c3 = 0ull;
        #pragma unroll
        for (int kk = 0; kk < 16; kk++) {
            ulonglong2 ha = h2v[2 * kk];
            ulonglong2 hb = h2v[2 * kk + 1];
            FMA2(c0, w2[4 * kk + 0], ha.x);
            FMA2(c1, w2[4 * kk + 1], ha.y);
            FMA2(c2, w2[4 * kk + 2], hb.x);
            FMA2(c3, w2[4 * kk + 3], hb.y);
        }
        hh_s[j] = bh + ((sum2(c0) + sum2(c1)) + (sum2(c2) + sum2(c3)));
        __syncthreads();

        if (j < 128) {
            float r = sigmf(pr + hh_s[j]);
            float z = sigmf(pz + hh_s[128 + j]);
            float n = tanhf_fast(pn + r * hh_s[256 + j]);
            float h = (1.f - z) * n + z * h_s[j];
            h_s[j] = h;
            float gc = fminf(fmaxf(h, -CLIPV), CLIPV);
            int tt = dir ? (T_STEPS - 1 - t) : t;
            g_g[((size_t)tt * BATCH + b) * (2 * EDIM) + dir * EDIM + j] = gc;
        }
        __syncthreads();
        pr = npr; pz = npz; pn = npn;
    }
}

// ---------------------------------------------------------------------------------
// Controller scan — spike(t-1) folded into hh-dot(t) phase (spike phase removed
// from the serial chain). Otherwise identical to R11's 4-phase structure.
// ---------------------------------------------------------------------------------
#define CTRL_SMEM_FLOATS 40832
#define CTRL_SMEM_BYTES  (CTRL_SMEM_FLOATS * 4)

__global__ __launch_bounds__(384, 1) void ctrl_scan(
    const float* __restrict__ factors, const float* __restrict__ eps,
    const float* __restrict__ Whh, const float* __restrict__ bhh,
    const float* __restrict__ cinit,
    const float* __restrict__ W_mu, const float* __restrict__ b_mu,
    const float* __restrict__ W_lv, const float* __restrict__ b_lv,
    const float* __restrict__ W_spk, const float* __restrict__ b_spk,
    const float* __restrict__ gain_p, const float* __restrict__ biasp_p,
    const float* __restrict__ logtau_p,
    float* __restrict__ out)
{
    extern __shared__ __align__(16) float smf[];
    float* wml  = smf;            // 128 x 132
    float* wspk = smf + 16896;    // 300 x 76
    float* h_s  = smf + 39696;    // 128
    float* hh_s = smf + 39824;    // 384
    float* mlv  = smf + 40208;    // 128
    float* gen  = smf + 40336;    // 68 (16B aligned)
    float* bml  = smf + 40404;    // 128
    float* bsp  = smf + 40532;    // 300

    const int j = threadIdx.x;
    const int b = blockIdx.x;

    unsigned long long w2[64];
    {
        const unsigned long long* wr = (const unsigned long long*)(Whh + j * 128);
        #pragma unroll
        for (int k = 0; k < 64; k++) w2[k] = wr[k];
    }
    const float bh = bhh[j];

    for (int idx = j; idx < 128 * 128; idx += 384) {
        int r = idx >> 7, k = idx & 127;
        wml[r * 132 + k] = (r < 64) ? W_mu[r * 128 + k] : W_lv[(r - 64) * 128 + k];
    }
    for (int idx = j; idx < 300 * 68; idx += 384) {
        int r = idx / 68, k = idx - r * 68;
        wspk[r * 76 + k] = W_spk[idx];
    }
    if (j < 128) { bml[j] = (j < 64) ? b_mu[j] : b_lv[j - 64]; h_s[j] = cinit[j]; }
    if (j < 300) bsp[j] = b_spk[j];

    const float gain  = gain_p[0];
    const float biasp = biasp_p[0];
    const float decay = 1.f - expf(-logtau_p[0]);
    float cal = 0.f;
    __syncthreads();

    const ulonglong2* h2v = (const ulonglong2*)h_s;
    const ulonglong2* g2v = (const ulonglong2*)gen;
    const float bspj = (j < NIN) ? bsp[j] : 0.f;

    float pr = 0.f, pz = 0.f, pn = 0.f, ev = 0.f, fv = 0.f;
    {
        const float* cpr = g_cp + (size_t)b * G3E;
        if (j < 128) { pr = cpr[j]; pz = cpr[128 + j]; pn = cpr[256 + j]; }
        if (j < UDIM) ev = eps[(size_t)b * UDIM + j];
        else if (j < UDIM + FDIM) fv = factors[(size_t)b * FDIM + (j - UDIM)];
    }

    for (int t = 0; t < T_STEPS; t++) {
        size_t row = (size_t)t * BATCH + b;

        float npr = 0.f, npz = 0.f, npn = 0.f, nev = 0.f, nfv = 0.f;
        if (t + 1 < T_STEPS) {
            size_t nrow = row + BATCH;
            const float* cpr = g_cp + nrow * G3E;
            if (j < 128) { npr = cpr[j]; npz = cpr[128 + j]; npn = cpr[256 + j]; }
            if (j < UDIM) nev = eps[nrow * UDIM + j];
            else if (j < UDIM + FDIM) nfv = factors[nrow * FDIM + (j - UDIM)];
        }

        // ---- phase A: spike/calcium for t-1 (overlapped) + hh dot for t ----
        if (t > 0 && j < NIN) {
            unsigned long long s01 = 0ull, s23 = 0ull;
            const ulonglong2* wr2 = (const ulonglong2*)&wspk[j * 76];
            #pragma unroll
            for (int kk = 0; kk < 17; kk++) {
                ulonglong2 wv = wr2[kk];
                ulonglong2 gv = g2v[kk];
                FMA2(s01, wv.x, gv.x);
                FMA2(s23, wv.y, gv.y);
            }
            float logit = bspj + (sum2(s01) + sum2(s23));
            float spike = fmaxf(__expf(logit) - 1.f, 0.f);
            cal = cal * decay + gain * spike + biasp;
            out[(row - BATCH) * NIN + j] = cal;
        }

        unsigned long long c0 = 0ull, c1 = 0ull, c2 = 0ull, c3 = 0ull;
        #pragma unroll
        for (int kk = 0; kk < 16; kk++) {
            ulonglong2 ha = h2v[2 * kk];
            ulonglong2 hb = h2v[2 * kk + 1];
            FMA2(c0, w2[4 * kk + 0], ha.x);
            FMA2(c1, w2[4 * kk + 1], ha.y);
            FMA2(c2, w2[4 * kk + 2], hb.x);
            FMA2(c3, w2[4 * kk + 3], hb.y);
        }
        hh_s[j] = bh + ((sum2(c0) + sum2(c1)) + (sum2(c2) + sum2(c3)));
        __syncthreads();

        // ---- phase B: gates, clip ----
        if (j < 128) {
            float r = sigmf(pr + hh_s[j]);
            float z = sigmf(pz + hh_s[128 + j]);
            float n = tanhf_fast(pn + r * hh_s[256 + j]);
            float h = (1.f - z) * n + z * h_s[j];
            h = fminf(fmaxf(h, -CLIPV), CLIPV);
            h_s[j] = h;
        }
        __syncthreads();

        // ---- phase C: mu (j<64) / lv (64<=j<128) ----
        if (j < 128) {
            unsigned long long m0 = 0ull, m1 = 0ull, m2 = 0ull, m3 = 0ull;
            const ulonglong2* wr2 = (const ulonglong2*)&wml[j * 132];
            #pragma unroll
            for (int kk = 0; kk < 16; kk++) {
                ulonglong2 wa = wr2[2 * kk];
                ulonglong2 wb = wr2[2 * kk + 1];
                ulonglong2 ha = h2v[2 * kk];
                ulonglong2 hb = h2v[2 * kk + 1];
                FMA2(m0, wa.x, ha.x);
                FMA2(m1, wa.y, ha.y);
                FMA2(m2, wb.x, hb.x);
                FMA2(m3, wb.y, hb.y);
            }
            mlv[j] = bml[j] + ((sum2(m0) + sum2(m1)) + (sum2(m2) + sum2(m3)));
        }
        __syncthreads();

        // ---- phase D: u = mu + exp(0.5 lv) * eps ; gen = [u, f] ----
        if (j < UDIM) gen[j] = mlv[j] + __expf(0.5f * mlv[UDIM + j]) * ev;
        else if (j < UDIM + FDIM) gen[j] = fv;
        __syncthreads();

        pr = npr; pz = npz; pn = npn; ev = nev; fv = nfv;
    }

    // final spike/calcium for t = T_STEPS-1
    if (j < NIN) {
        unsigned long long s01 = 0ull, s23 = 0ull;
        const ulonglong2* wr2 = (const ulonglong2*)&wspk[j * 76];
        #pragma unroll
        for (int kk = 0; kk < 17; kk++) {
            ulonglong2 wv = wr2[kk];
            ulonglong2 gv = g2v[kk];
            FMA2(s01, wv.x, gv.x);
            FMA2(s23, wv.y, gv.y);
        }
        float logit = bspj + (sum2(s01) + sum2(s23));
        float spike = fmaxf(__expf(logit) - 1.f, 0.f);
        cal = cal * decay + gain * spike + biasp;
        out[((size_t)(T_STEPS - 1) * BATCH + b) * NIN + j] = cal;
    }
}

// ---------------------------------------------------------------------------------
extern "C" void kernel_launch(void* const* d_in, const int* in_sizes, int n_in,
                              void* d_out, int out_size)
{
    (void)in_sizes; (void)n_in; (void)out_size;
    const float* x       = (const float*)d_in[0];
    const float* factors = (const float*)d_in[1];
    const float* eps     = (const float*)d_in[2];
    const float* eWihf   = (const float*)d_in[3];
    const float* eWhhf   = (const float*)d_in[4];
    const float* ebihf   = (const float*)d_in[5];
    const float* ebhhf   = (const float*)d_in[6];
    const float* eWihb   = (const float*)d_in[7];
    const float* eWhhb   = (const float*)d_in[8];
    const float* ebihb   = (const float*)d_in[9];
    const float* ebhhb   = (const float*)d_in[10];
    const float* einit   = (const float*)d_in[11];
    const float* cWih    = (const float*)d_in[12];
    const float* cWhh    = (const float*)d_in[13];
    const float* cbih    = (const float*)d_in[14];
    const float* cbhh    = (const float*)d_in[15];
    const float* cinit   = (const float*)d_in[16];
    const float* Wmu     = (const float*)d_in[17];
    const float* bmu     = (const float*)d_in[18];
    const float* Wlv     = (const float*)d_in[19];
    const float* blv     = (const float*)d_in[20];
    const float* Wspk    = (const float*)d_in[21];
    const float* bspk    = (const float*)d_in[22];
    const float* gain    = (const float*)d_in[23];
    const float* bp      = (const float*)d_in[24];
    const float* ltau    = (const float*)d_in[25];
    float* out = (float*)d_out;

    float *xpf, *xpb, *gg, *cp;
    cudaGetSymbolAddress((void**)&xpf, g_xpf);
    cudaGetSymbolAddress((void**)&xpb, g_xpb);
    cudaGetSymbolAddress((void**)&gg,  g_g);
    cudaGetSymbolAddress((void**)&cp,  g_cp);

    uint2 *xh, *gh, *wfh, *wfl, *wbh, *wbl, *wch, *wcl;
    cudaGetSymbolAddress((void**)&xh, g_xh);
    cudaGetSymbolAddress((void**)&gh, g_gh);
    cudaGetSymbolAddress((void**)&wfh, g_wfh); cudaGetSymbolAddress((void**)&wfl, g_wfl);
    cudaGetSymbolAddress((void**)&wbh, g_wbh); cudaGetSymbolAddress((void**)&wbl, g_wbl);
    cudaGetSymbolAddress((void**)&wch, g_wch); cudaGetSymbolAddress((void**)&wcl, g_wcl);

    cudaFuncSetAttribute(gemm_mma, cudaFuncAttributeMaxDynamicSharedMemorySize, GEMM_SMEM);
    cudaFuncSetAttribute(ctrl_scan, cudaFuncAttributeMaxDynamicSharedMemorySize, CTRL_SMEM_BYTES);

    dim3 gemm_grid(T_STEPS, G3E / 128);

    conv_half<<<(XN4 + 255) / 256, 256>>>((const float4*)x, xh, XN4);
    conv_half_split<<<(WFN4 + 255) / 256, 256>>>((const float4*)eWihf, wfh, wfl, WFN4);
    conv_half_split<<<(WFN4 + 255) / 256, 256>>>((const float4*)eWihb, wbh, wbl, WFN4);
    gemm_mma<<<gemm_grid, 256, GEMM_SMEM>>>(xh, NIN, nullptr, 0, wfh, wfl, ebihf, xpf, 0);
    conv_half_split<<<(WCN4 + 255) / 256, 256>>>((const float4*)cWih, wch, wcl, WCN4);
    gemm_mma<<<gemm_grid, 256, GEMM_SMEM>>>(xh, NIN, nullptr, 0, wbh, wbl, ebihb, xpb, 1);

    // bidirectional encoder scan -> g (256 CTAs, 1 row/CTA — R11 config)
    enc_scan<<<256, 384>>>(eWhhf, ebhhf, eWhhb, ebhhb, einit);

    // convert g, then cp = [g, x] @ ctrl_Wih^T + b
    conv_half<<<(GN4 + 255) / 256, 256>>>((const float4*)gg, gh, GN4);
    gemm_mma<<<gemm_grid, 256, GEMM_SMEM>>>(gh, 2 * EDIM, xh, NIN, wch, wcl, cbih, cp, 0);

    // controller scan -> calcium (d_out)
    ctrl_scan<<<128, 384, CTRL_SMEM_BYTES>>>(factors, eps, cWhh, cbhh, cinit,
                                             Wmu, bmu, Wlv, blv, Wspk, bspk,
                                             gain, bp, ltau, out);
}

// round 14
// speedup vs baseline: 1.5481x; 1.3922x over previous
#include <cuda_runtime.h>
#include <cuda_fp16.h>
#include <cstdint>
#include <cstddef>

#define T_STEPS 500
#define BATCH   128
#define NIN     300
#define EDIM    128
#define CDIM    128
#define UDIM    64
#define FDIM    4
#define G3E     384      // 3*E == 3*C
#define CLIPV   5.0f
#define NROWS   (T_STEPS * BATCH)      // 64000
#define KGEN    72                     // padded gen width (68 -> 72)

// ---------------- scratch (device globals; zero-initialized, no runtime alloc) ----
__device__ float g_xpf[(size_t)NROWS * G3E];     // xp_f, later reused for mlv out
__device__ float g_xpb[(size_t)NROWS * G3E];     // xp_b, later reused for spike logits
__device__ float g_g  [(size_t)NROWS * 2 * EDIM];
__device__ float g_cp [(size_t)NROWS * G3E];

#define XN4   (NROWS * NIN / 4)
#define GN4   (NROWS * 2 * EDIM / 4)
#define WFN4  (G3E * NIN / 4)
#define WCN4  (G3E * (2 * EDIM + NIN) / 4)
#define WMN4  (UDIM * CDIM / 4)                  // 2048 per mu/lv half
__device__ uint2 g_xh[XN4];
__device__ uint2 g_gh[GN4];
__device__ uint2 g_wfh[WFN4], g_wfl[WFN4];
__device__ uint2 g_wbh[WFN4], g_wbl[WFN4];
__device__ uint2 g_wch[WCN4], g_wcl[WCN4];
__device__ uint2 g_wmh[2 * WMN4], g_wml[2 * WMN4];       // [128,128] combined mu/lv
__device__ uint2 g_wsh[384 * KGEN / 4], g_wsl[384 * KGEN / 4]; // W_spk padded [384,72]
__device__ uint2 g_hfu[(size_t)NROWS * CDIM / 4];        // h(t) fp16
__device__ uint2 g_genh[(size_t)NROWS * KGEN / 4];       // gen fp16 padded
__device__ float g_zero[384];                            // zero bias

// ---------------- packed f32x2 helpers ----------------
#define FMA2(acc, a, b) \
    asm volatile("fma.rn.f32x2 %0, %1, %2, %0;" : "+l"(acc) : "l"(a), "l"(b))

__device__ __forceinline__ float sum2(unsigned long long v) {
    float lo, hi;
    asm("mov.b64 {%0, %1}, %2;" : "=f"(lo), "=f"(hi) : "l"(v));
    return lo + hi;
}

__device__ __forceinline__ float sigmf(float x) {
    return __fdividef(1.0f, 1.0f + __expf(-x));
}

__device__ __forceinline__ float tanhf_fast(float x) {
    x = fminf(fmaxf(x, -15.f), 15.f);
    float e = __expf(2.0f * x);
    return __fdividef(e - 1.0f, e + 1.0f);
}

// =================================================================================
// fp32 -> fp16 conversions
// =================================================================================
__device__ __forceinline__ uint32_t packh2(__half a, __half b) {
    return ((uint32_t)__half_as_ushort(b) << 16) | __half_as_ushort(a);
}

__global__ __launch_bounds__(256) void conv_half(
    const float4* __restrict__ src, uint2* __restrict__ dst, int n4)
{
    int i = blockIdx.x * 256 + threadIdx.x;
    if (i >= n4) return;
    float4 v = src[i];
    dst[i] = make_uint2(packh2(__float2half_rn(v.x), __float2half_rn(v.y)),
                        packh2(__float2half_rn(v.z), __float2half_rn(v.w)));
}

__global__ __launch_bounds__(256) void conv_half_split(
    const float4* __restrict__ src, uint2* __restrict__ hi, uint2* __restrict__ lo, int n4)
{
    int i = blockIdx.x * 256 + threadIdx.x;
    if (i >= n4) return;
    float4 v = src[i];
    __half h0 = __float2half_rn(v.x);
    __half h1 = __float2half_rn(v.y);
    __half h2 = __float2half_rn(v.z);
    __half h3 = __float2half_rn(v.w);
    hi[i] = make_uint2(packh2(h0, h1), packh2(h2, h3));
    __half l0 = __float2half_rn(v.x - __half2float(h0));
    __half l1 = __float2half_rn(v.y - __half2float(h1));
    __half l2 = __float2half_rn(v.z - __half2float(h2));
    __half l3 = __float2half_rn(v.w - __half2float(h3));
    lo[i] = make_uint2(packh2(l0, l1), packh2(l2, l3));
}

// W_spk [300,68] -> padded [300,72] hi/lo (rows 300..383 stay zero-init)
__global__ __launch_bounds__(256) void conv_wspk(
    const float* __restrict__ W, uint2* __restrict__ hi, uint2* __restrict__ lo)
{
    int idx = blockIdx.x * 256 + threadIdx.x;   // over 300 * 18
    if (idx >= 300 * (KGEN / 4)) return;
    int row = idx / (KGEN / 4);
    int c4 = idx - row * (KGEN / 4);
    float v[4];
    #pragma unroll
    for (int q = 0; q < 4; q++) {
        int k = c4 * 4 + q;
        v[q] = (k < UDIM + FDIM) ? W[row * (UDIM + FDIM) + k] : 0.f;
    }
    __half h0 = __float2half_rn(v[0]), h1 = __float2half_rn(v[1]);
    __half h2 = __float2half_rn(v[2]), h3 = __float2half_rn(v[3]);
    hi[idx] = make_uint2(packh2(h0, h1), packh2(h2, h3));
    __half l0 = __float2half_rn(v[0] - __half2float(h0));
    __half l1 = __float2half_rn(v[1] - __half2float(h1));
    __half l2 = __float2half_rn(v[2] - __half2float(h2));
    __half l3 = __float2half_rn(v[3] - __half2float(h3));
    lo[idx] = make_uint2(packh2(l0, l1), packh2(l2, l3));
}

// =================================================================================
// Tensor-core GEMM: fp16 split-2, 2 passes; now with cstride/cmax for small outputs.
// =================================================================================
#define BKT 64
#define TPAD 72
#define TILE_B (128 * TPAD * 2)
#define STAGE_B (3 * TILE_B)
#define SMG_BASE 1024
#define GEMM_SMEM (SMG_BASE + 2 * STAGE_B)   // 111616 -> 2 CTAs/SM

__device__ __forceinline__ uint32_t smem_u32(const void* p) {
    uint32_t a;
    asm("{ .reg .u64 t; cvta.to.shared.u64 t, %1; cvt.u32.u64 %0, t; }" : "=r"(a) : "l"(p));
    return a;
}

__device__ __forceinline__ void ldm_x4(uint32_t* r, uint32_t addr) {
    asm volatile("ldmatrix.sync.aligned.m8n8.x4.shared.b16 {%0,%1,%2,%3}, [%4];"
                 : "=r"(r[0]), "=r"(r[1]), "=r"(r[2]), "=r"(r[3]) : "r"(addr));
}

__device__ __forceinline__ void mma_fp16(float* d, const uint32_t* a, uint32_t b0, uint32_t b1) {
    asm volatile(
        "mma.sync.aligned.m16n8k16.row.col.f32.f16.f16.f32 "
        "{%0,%1,%2,%3}, {%4,%5,%6,%7}, {%8,%9}, {%0,%1,%2,%3};"
        : "+f"(d[0]), "+f"(d[1]), "+f"(d[2]), "+f"(d[3])
        : "r"(a[0]), "r"(a[1]), "r"(a[2]), "r"(a[3]), "r"(b0), "r"(b1));
}

__device__ __forceinline__ void cp_tile(
    const __half* __restrict__ src, int stride, int row0,
    int kbase, int kmax, uint32_t smDst, int tid)
{
    #pragma unroll
    for (int i = 0; i < 8; i++) {
        int idx = i * 256 + tid;
        int r = idx >> 4, c4 = idx & 15;
        int kg = kbase + c4 * 4;
        int sz = (kg < kmax) ? 8 : 0;
        int kgc = (kg < kmax) ? kg : 0;
        size_t off = (size_t)(row0 + r) * stride + kgc;
        uint32_t so = (uint32_t)(r * TPAD + c4 * 4) * 2;
        asm volatile("cp.async.ca.shared.global [%0], [%1], 8, %2;"
                     :: "r"(smDst + so), "l"(src + off), "r"(sz));
    }
}

__global__ __launch_bounds__(256, 2) void gemm_mma(
    const uint2* Ah0u, int K0, const uint2* Ah1u, int K1,
    const uint2* Whiu, const uint2* Wlou,
    const float* __restrict__ bias, float* __restrict__ C, int reverse,
    int cstride, int cmax)
{
    extern __shared__ char sm[];
    const __half* Ah0 = (const __half*)Ah0u;
    const __half* Ah1 = (const __half*)Ah1u;
    const __half* Whi = (const __half*)Whiu;
    const __half* Wlo = (const __half*)Wlou;

    const int tid  = threadIdx.x;
    const int warp = tid >> 5, lane = tid & 31;
    const int tb = blockIdx.x;
    const int n0 = blockIdx.y * 128;
    const int Ktot = K0 + K1;
    const int nkt = (Ktot + BKT - 1) / BKT;

    const int m0w = (warp >> 1) * 32;
    const int n0w = (warp & 1) * 64;
    const int laneRow  = lane & 15;
    const int laneHalf = lane >> 4;

    float* biass = (float*)sm;
    if (tid < 128) biass[tid] = bias[n0 + tid];

    const int arow0 = (reverse ? (T_STEPS - 1 - tb) : tb) * BATCH;
    const int crow0 = tb * BATCH;

    const uint32_t smBase = smem_u32(sm + SMG_BASE);

    float acc[2][8][4];
    #pragma unroll
    for (int mi = 0; mi < 2; mi++)
        #pragma unroll
        for (int nf = 0; nf < 8; nf++)
            #pragma unroll
            for (int q = 0; q < 4; q++) acc[mi][nf][q] = 0.f;

    auto issue_tile = [&](int kt) {
        const int k0 = kt * BKT;
        const uint32_t stg = smBase + (uint32_t)(kt & 1) * STAGE_B;
        if (k0 < K0)
            cp_tile(Ah0, K0, arow0, k0, K0, stg, tid);
        else
            cp_tile(Ah1, K1, arow0, k0 - K0, K1, stg, tid);
        cp_tile(Whi, Ktot, n0, k0, Ktot, stg + TILE_B, tid);
        cp_tile(Wlo, Ktot, n0, k0, Ktot, stg + 2 * TILE_B, tid);
    };

    issue_tile(0);
    asm volatile("cp.async.commit_group;" ::: "memory");

    for (int kt = 0; kt < nkt; kt++) {
        if (kt + 1 < nkt) issue_tile(kt + 1);
        asm volatile("cp.async.commit_group;" ::: "memory");
        asm volatile("cp.async.wait_group 1;" ::: "memory");
        __syncthreads();

        const uint32_t stg = smBase + (uint32_t)(kt & 1) * STAGE_B;
        const uint32_t sbA   = stg;
        const uint32_t sbBHI = stg + TILE_B;
        const uint32_t sbBLO = stg + 2 * TILE_B;

        #pragma unroll
        for (int ks = 0; ks < 4; ks++) {
            const uint32_t colb = (uint32_t)(ks * 16 + laneHalf * 8) * 2;

            uint32_t ah[2][4];
            #pragma unroll
            for (int mi = 0; mi < 2; mi++) {
                uint32_t ro = (uint32_t)(m0w + mi * 16 + laneRow) * (TPAD * 2) + colb;
                ldm_x4(ah[mi], sbA + ro);
            }
            uint32_t bh[8][2], bl[8][2];
            #pragma unroll
            for (int ni = 0; ni < 4; ni++) {
                uint32_t ro = (uint32_t)(n0w + ni * 16 + laneRow) * (TPAD * 2) + colb;
                uint32_t rb[4];
                ldm_x4(rb, sbBHI + ro);
                bh[2 * ni][0] = rb[0]; bh[2 * ni][1] = rb[2];
                bh[2 * ni + 1][0] = rb[1]; bh[2 * ni + 1][1] = rb[3];
                ldm_x4(rb, sbBLO + ro);
                bl[2 * ni][0] = rb[0]; bl[2 * ni][1] = rb[2];
                bl[2 * ni + 1][0] = rb[1]; bl[2 * ni + 1][1] = rb[3];
            }
            #pragma unroll
            for (int mi = 0; mi < 2; mi++)
                #pragma unroll
                for (int nf = 0; nf < 8; nf++)
                    mma_fp16(acc[mi][nf], ah[mi], bh[nf][0], bh[nf][1]);
            #pragma unroll
            for (int mi = 0; mi < 2; mi++)
                #pragma unroll
                for (int nf = 0; nf < 8; nf++)
                    mma_fp16(acc[mi][nf], ah[mi], bl[nf][0], bl[nf][1]);
        }
        __syncthreads();
    }

    float* stage = (float*)(sm + SMG_BASE);
    {
        const int g = lane >> 2, t4 = lane & 3;
        #pragma unroll
        for (int mi = 0; mi < 2; mi++)
            #pragma unroll
            for (int nf = 0; nf < 8; nf++) {
                int col = n0w + nf * 8 + 2 * t4;
                float* p0 = &stage[(m0w + mi * 16 + g) * 132 + col];
                float* p1 = &stage[(m0w + mi * 16 + g + 8) * 132 + col];
                p0[0] = acc[mi][nf][0]; p0[1] = acc[mi][nf][1];
                p1[0] = acc[mi][nf][2]; p1[1] = acc[mi][nf][3];
            }
    }
    __syncthreads();
    {
        const int col = tid & 127;
        if (n0 + col < cmax) {
            const float bcol = biass[col];
            #pragma unroll 4
            for (int it = 0; it < 64; it++) {
                int r = it * 2 + (tid >> 7);
                C[(size_t)(crow0 + r) * cstride + n0 + col] = stage[r * 132 + col] + bcol;
            }
        }
    }
}

// ---------------------------------------------------------------------------------
// Encoder bidirectional GRU scan — unchanged (R11/R13 version).
// ---------------------------------------------------------------------------------
__global__ __launch_bounds__(384, 1) void enc_scan(
    const float* __restrict__ Whh_f, const float* __restrict__ bhh_f,
    const float* __restrict__ Whh_b, const float* __restrict__ bhh_b,
    const float* __restrict__ enc_init)
{
    const int j = threadIdx.x;
    const int dir = blockIdx.x >> 7;
    const int b = blockIdx.x & 127;
    const float* Whh = dir ? Whh_b : Whh_f;
    const float* bhh = dir ? bhh_b : bhh_f;
    const float* xp = dir ? g_xpb : g_xpf;

    unsigned long long w2[64];
    {
        const unsigned long long* wr = (const unsigned long long*)(Whh + j * 128);
        #pragma unroll
        for (int k = 0; k < 64; k++) w2[k] = wr[k];
    }
    const float bh = bhh[j];

    __shared__ __align__(16) float h_s[128];
    __shared__ float hh_s[384];
    if (j < 128) h_s[j] = enc_init[dir * 128 + j];
    __syncthreads();

    const ulonglong2* h2v = (const ulonglong2*)h_s;

    float pr = 0.f, pz = 0.f, pn = 0.f;
    if (j < 128) {
        const float* xr = xp + (size_t)b * G3E;
        pr = xr[j]; pz = xr[128 + j]; pn = xr[256 + j];
    }

    for (int t = 0; t < T_STEPS; t++) {
        float npr = 0.f, npz = 0.f, npn = 0.f;
        if (t + 1 < T_STEPS && j < 128) {
            const float* xr = xp + ((size_t)(t + 1) * BATCH + b) * G3E;
            npr = xr[j]; npz = xr[128 + j]; npn = xr[256 + j];
        }

        unsigned long long c0 = 0ull, c1 = 0ull, c2 = 0ull, c3 = 0ull;
        #pragma unroll
        for (int kk = 0; kk < 16; kk++) {
            ulonglong2 ha = h2v[2 * kk];
            ulonglong2 hb = h2v[2 * kk + 1];
            FMA2(c0, w2[4 * kk + 0], ha.x);
            FMA2(c1, w2[4 * kk + 1], ha.y);
            FMA2(c2, w2[4 * kk + 2], hb.x);
            FMA2(c3, w2[4 * kk + 3], hb.y);
        }
        hh_s[j] = bh + ((sum2(c0) + sum2(c1)) + (sum2(c2) + sum2(c3)));
        __syncthreads();

        if (j < 128) {
            float r = sigmf(pr + hh_s[j]);
            float z = sigmf(pz + hh_s[128 + j]);
            float n = tanhf_fast(pn + r * hh_s[256 + j]);
            float h = (1.f - z) * n + z * h_s[j];
            h_s[j] = h;
            float gc = fminf(fmaxf(h, -CLIPV), CLIPV);
            int tt = dir ? (T_STEPS - 1 - t) : t;
            g_g[((size_t)tt * BATCH + b) * (2 * EDIM) + dir * EDIM + j] = gc;
        }
        __syncthreads();
        pr = npr; pz = npz; pn = npn;
    }
}

// ---------------------------------------------------------------------------------
// Controller scan — PURE GRU (2 barriers/step); stores clipped h(t) as fp16.
// Everything downstream (mu/lv, gen, spike, calcium) hoisted into batched kernels.
// ---------------------------------------------------------------------------------
__global__ __launch_bounds__(384, 1) void ctrl_scan(
    const float* __restrict__ Whh, const float* __restrict__ bhh,
    const float* __restrict__ cinit)
{
    const int j = threadIdx.x;
    const int b = blockIdx.x;

    unsigned long long w2[64];
    {
        const unsigned long long* wr = (const unsigned long long*)(Whh + j * 128);
        #pragma unroll
        for (int k = 0; k < 64; k++) w2[k] = wr[k];
    }
    const float bh = bhh[j];

    __shared__ __align__(16) float h_s[128];
    __shared__ float hh_s[384];
    if (j < 128) h_s[j] = cinit[j];
    __syncthreads();

    const ulonglong2* h2v = (const ulonglong2*)h_s;
    __half* hf = (__half*)g_hfu;

    float pr = 0.f, pz = 0.f, pn = 0.f;
    if (j < 128) {
        const float* cpr = g_cp + (size_t)b * G3E;
        pr = cpr[j]; pz = cpr[128 + j]; pn = cpr[256 + j];
    }

    for (int t = 0; t < T_STEPS; t++) {
        size_t row = (size_t)t * BATCH + b;
        float npr = 0.f, npz = 0.f, npn = 0.f;
        if (t + 1 < T_STEPS && j < 128) {
            const float* cpr = g_cp + (row + BATCH) * G3E;
            npr = cpr[j]; npz = cpr[128 + j]; npn = cpr[256 + j];
        }

        unsigned long long c0 = 0ull, c1 = 0ull, c2 = 0ull, c3 = 0ull;
        #pragma unroll
        for (int kk = 0; kk < 16; kk++) {
            ulonglong2 ha = h2v[2 * kk];
            ulonglong2 hb = h2v[2 * kk + 1];
            FMA2(c0, w2[4 * kk + 0], ha.x);
            FMA2(c1, w2[4 * kk + 1], ha.y);
            FMA2(c2, w2[4 * kk + 2], hb.x);
            FMA2(c3, w2[4 * kk + 3], hb.y);
        }
        hh_s[j] = bh + ((sum2(c0) + sum2(c1)) + (sum2(c2) + sum2(c3)));
        __syncthreads();

        if (j < 128) {
            float r = sigmf(pr + hh_s[j]);
            float z = sigmf(pz + hh_s[128 + j]);
            float n = tanhf_fast(pn + r * hh_s[256 + j]);
            float h = (1.f - z) * n + z * h_s[j];
            h = fminf(fmaxf(h, -CLIPV), CLIPV);
            h_s[j] = h;
            hf[row * CDIM + j] = __float2half_rn(h);
        }
        __syncthreads();
        pr = npr; pz = npz; pn = npn;
    }
}

// ---------------------------------------------------------------------------------
// gen kernel: u = (mu+bmu) + exp(0.5(lv+blv))*eps ; gen = [u, f, 0pad] as fp16
// mlv layout: [64000, 128] (cols 0..63 mu, 64..127 lv), from gemm into g_xpf.
// ---------------------------------------------------------------------------------
__global__ __launch_bounds__(256) void gen_kernel(
    const float* __restrict__ mlv, const float* __restrict__ eps,
    const float* __restrict__ factors,
    const float* __restrict__ bmu, const float* __restrict__ blv)
{
    int idx = blockIdx.x * 256 + threadIdx.x;     // over NROWS * KGEN
    if (idx >= NROWS * KGEN) return;
    int row = idx / KGEN;
    int j = idx - row * KGEN;
    float v = 0.f;
    if (j < UDIM) {
        float mu = mlv[(size_t)row * 128 + j] + bmu[j];
        float lv = mlv[(size_t)row * 128 + UDIM + j] + blv[j];
        v = mu + __expf(0.5f * lv) * eps[(size_t)row * UDIM + j];
    } else if (j < UDIM + FDIM) {
        v = factors[(size_t)row * FDIM + (j - UDIM)];
    }
    ((__half*)g_genh)[idx] = __float2half_rn(v);
}

// ---------------------------------------------------------------------------------
// calcium kernel: per (b,n) AR1 over t, batched loads (MLP=4).
// logits in g_xpb layout [row=t*128+b, 300].
// ---------------------------------------------------------------------------------
__global__ __launch_bounds__(128) void calcium_kernel(
    const float* __restrict__ logits, const float* __restrict__ bspk,
    const float* __restrict__ gain_p, const float* __restrict__ biasp_p,
    const float* __restrict__ ltau_p, float* __restrict__ out)
{
    int idx = blockIdx.x * 128 + threadIdx.x;     // over BATCH*NIN = 38400
    if (idx >= BATCH * NIN) return;
    const int n = idx % NIN;
    const float bsp = bspk[n];
    const float gain = gain_p[0];
    const float biasp = biasp_p[0];
    const float decay = 1.f - expf(-ltau_p[0]);
    float cal = 0.f;
    const size_t stride = (size_t)BATCH * NIN;
    const float* lp = logits + idx;
    float* op = out + idx;
    for (int t = 0; t < T_STEPS; t += 4) {
        float l0 = lp[(size_t)(t + 0) * stride];
        float l1 = lp[(size_t)(t + 1) * stride];
        float l2 = lp[(size_t)(t + 2) * stride];
        float l3 = lp[(size_t)(t + 3) * stride];
        float s;
        s = fmaxf(__expf(l0 + bsp) - 1.f, 0.f); cal = cal * decay + gain * s + biasp;
        op[(size_t)(t + 0) * stride] = cal;
        s = fmaxf(__expf(l1 + bsp) - 1.f, 0.f); cal = cal * decay + gain * s + biasp;
        op[(size_t)(t + 1) * stride] = cal;
        s = fmaxf(__expf(l2 + bsp) - 1.f, 0.f); cal = cal * decay + gain * s + biasp;
        op[(size_t)(t + 2) * stride] = cal;
        s = fmaxf(__expf(l3 + bsp) - 1.f, 0.f); cal = cal * decay + gain * s + biasp;
        op[(size_t)(t + 3) * stride] = cal;
    }
}

// ---------------------------------------------------------------------------------
extern "C" void kernel_launch(void* const* d_in, const int* in_sizes, int n_in,
                              void* d_out, int out_size)
{
    (void)in_sizes; (void)n_in; (void)out_size;
    const float* x       = (const float*)d_in[0];
    const float* factors = (const float*)d_in[1];
    const float* eps     = (const float*)d_in[2];
    const float* eWihf   = (const float*)d_in[3];
    const float* eWhhf   = (const float*)d_in[4];
    const float* ebihf   = (const float*)d_in[5];
    const float* ebhhf   = (const float*)d_in[6];
    const float* eWihb   = (const float*)d_in[7];
    const float* eWhhb   = (const float*)d_in[8];
    const float* ebihb   = (const float*)d_in[9];
    const float* ebhhb   = (const float*)d_in[10];
    const float* einit   = (const float*)d_in[11];
    const float* cWih    = (const float*)d_in[12];
    const float* cWhh    = (const float*)d_in[13];
    const float* cbih    = (const float*)d_in[14];
    const float* cbhh    = (const float*)d_in[15];
    const float* cinit   = (const float*)d_in[16];
    const float* Wmu     = (const float*)d_in[17];
    const float* bmu     = (const float*)d_in[18];
    const float* Wlv     = (const float*)d_in[19];
    const float* blv     = (const float*)d_in[20];
    const float* Wspk    = (const float*)d_in[21];
    const float* bspk    = (const float*)d_in[22];
    const float* gain    = (const float*)d_in[23];
    const float* bp      = (const float*)d_in[24];
    const float* ltau    = (const float*)d_in[25];
    float* out = (float*)d_out;

    float *xpf, *xpb, *gg, *cp, *zero;
    cudaGetSymbolAddress((void**)&xpf, g_xpf);
    cudaGetSymbolAddress((void**)&xpb, g_xpb);
    cudaGetSymbolAddress((void**)&gg,  g_g);
    cudaGetSymbolAddress((void**)&cp,  g_cp);
    cudaGetSymbolAddress((void**)&zero, g_zero);

    uint2 *xh, *gh, *wfh, *wfl, *wbh, *wbl, *wch, *wcl, *wmh, *wml, *wsh, *wsl, *hfu, *genh;
    cudaGetSymbolAddress((void**)&xh, g_xh);
    cudaGetSymbolAddress((void**)&gh, g_gh);
    cudaGetSymbolAddress((void**)&wfh, g_wfh); cudaGetSymbolAddress((void**)&wfl, g_wfl);
    cudaGetSymbolAddress((void**)&wbh, g_wbh); cudaGetSymbolAddress((void**)&wbl, g_wbl);
    cudaGetSymbolAddress((void**)&wch, g_wch); cudaGetSymbolAddress((void**)&wcl, g_wcl);
    cudaGetSymbolAddress((void**)&wmh, g_wmh); cudaGetSymbolAddress((void**)&wml, g_wml);
    cudaGetSymbolAddress((void**)&wsh, g_wsh); cudaGetSymbolAddress((void**)&wsl, g_wsl);
    cudaGetSymbolAddress((void**)&hfu, g_hfu);
    cudaGetSymbolAddress((void**)&genh, g_genh);

    cudaFuncSetAttribute(gemm_mma, cudaFuncAttributeMaxDynamicSharedMemorySize, GEMM_SMEM);

    dim3 gemm_grid(T_STEPS, G3E / 128);

    // ---- conversions ----
    conv_half<<<(XN4 + 255) / 256, 256>>>((const float4*)x, xh, XN4);
    conv_half_split<<<(WFN4 + 255) / 256, 256>>>((const float4*)eWihf, wfh, wfl, WFN4);
    conv_half_split<<<(WFN4 + 255) / 256, 256>>>((const float4*)eWihb, wbh, wbl, WFN4);
    conv_half_split<<<(WCN4 + 255) / 256, 256>>>((const float4*)cWih, wch, wcl, WCN4);
    conv_half_split<<<(WMN4 + 255) / 256, 256>>>((const float4*)Wmu, wmh, wml, WMN4);
    conv_half_split<<<(WMN4 + 255) / 256, 256>>>((const float4*)Wlv, wmh + WMN4, wml + WMN4, WMN4);
    conv_wspk<<<(300 * (KGEN / 4) + 255) / 256, 256>>>(Wspk, wsh, wsl);

    // ---- input-projection GEMMs ----
    gemm_mma<<<gemm_grid, 256, GEMM_SMEM>>>(xh, NIN, nullptr, 0, wfh, wfl, ebihf, xpf, 0, G3E, G3E);
    gemm_mma<<<gemm_grid, 256, GEMM_SMEM>>>(xh, NIN, nullptr, 0, wbh, wbl, ebihb, xpb, 1, G3E, G3E);

    // ---- bidirectional encoder scan -> g ----
    enc_scan<<<256, 384>>>(eWhhf, ebhhf, eWhhb, ebhhb, einit);

    // ---- cp = [g, x] @ ctrl_Wih^T + b ----
    conv_half<<<(GN4 + 255) / 256, 256>>>((const float4*)gg, gh, GN4);
    gemm_mma<<<gemm_grid, 256, GEMM_SMEM>>>(gh, 2 * EDIM, xh, NIN, wch, wcl, cbih, cp, 0, G3E, G3E);

    // ---- controller pure-GRU scan -> h fp16 ----
    ctrl_scan<<<128, 384>>>(cWhh, cbhh, cinit);

    // ---- mlv = h @ [Wmu;Wlv]^T  (out -> g_xpf reuse, stride 128) ----
    gemm_mma<<<dim3(T_STEPS, 1), 256, GEMM_SMEM>>>(hfu, CDIM, nullptr, 0,
                                                   wmh, wml, zero, xpf, 0, 128, 128);

    // ---- gen = [mu + exp(0.5 lv) eps, f, pad] fp16 ----
    gen_kernel<<<(NROWS * KGEN + 255) / 256, 256>>>(xpf, eps, factors, bmu, blv);

    // ---- spike logits = gen @ Wspk^T (out -> g_xpb reuse, stride 300) ----
    gemm_mma<<<dim3(T_STEPS, 3), 256, GEMM_SMEM>>>(genh, KGEN, nullptr, 0,
                                                   wsh, wsl, zero, xpb, 0, NIN, NIN);

    // ---- AR1 calcium -> out ----
    calcium_kernel<<<(BATCH * NIN + 127) / 128, 128>>>(xpb, bspk, gain, bp, ltau, out);
}

// round 15
// speedup vs baseline: 1.7342x; 1.1202x over previous
#include <cuda_runtime.h>
#include <cuda_fp16.h>
#include <cstdint>
#include <cstddef>

#define T_STEPS 500
#define BATCH   128
#define NIN     300
#define EDIM    128
#define CDIM    128
#define UDIM    64
#define FDIM    4
#define G3E     384      // 3*E == 3*C
#define CLIPV   5.0f
#define NROWS   (T_STEPS * BATCH)      // 64000
#define KGEN    72                     // padded gen width (68 -> 72)

// ---------------- scratch (device globals; zero-initialized, no runtime alloc) ----
__device__ float g_xpf[(size_t)NROWS * G3E];     // xp_f, later reused for mlv out
__device__ float g_xpb[(size_t)NROWS * G3E];     // xp_b, later reused for spike logits
__device__ float g_g  [(size_t)NROWS * 2 * EDIM];
__device__ float g_cp [(size_t)NROWS * G3E];

#define XN4   (NROWS * NIN / 4)
#define GN4   (NROWS * 2 * EDIM / 4)
#define WFN4  (G3E * NIN / 4)
#define WCN4  (G3E * (2 * EDIM + NIN) / 4)
#define WMN4  (UDIM * CDIM / 4)
__device__ uint2 g_xh[XN4];
__device__ uint2 g_gh[GN4];
__device__ uint2 g_wfh[WFN4], g_wfl[WFN4];
__device__ uint2 g_wbh[WFN4], g_wbl[WFN4];
__device__ uint2 g_wch[WCN4], g_wcl[WCN4];
__device__ uint2 g_wmh[2 * WMN4], g_wml[2 * WMN4];
__device__ uint2 g_wsh[384 * KGEN / 4], g_wsl[384 * KGEN / 4];
__device__ uint2 g_hfu[(size_t)NROWS * CDIM / 4];
__device__ uint2 g_genh[(size_t)NROWS * KGEN / 4];
__device__ float g_zero[384];

// ---------------- packed f32x2 helpers ----------------
#define FMA2(acc, a, b) \
    asm volatile("fma.rn.f32x2 %0, %1, %2, %0;" : "+l"(acc) : "l"(a), "l"(b))

__device__ __forceinline__ float sum2(unsigned long long v) {
    float lo, hi;
    asm("mov.b64 {%0, %1}, %2;" : "=f"(lo), "=f"(hi) : "l"(v));
    return lo + hi;
}

__device__ __forceinline__ float sigmf(float x) {
    return __fdividef(1.0f, 1.0f + __expf(-x));
}

__device__ __forceinline__ float tanhf_fast(float x) {
    x = fminf(fmaxf(x, -15.f), 15.f);
    float e = __expf(2.0f * x);
    return __fdividef(e - 1.0f, e + 1.0f);
}

// =================================================================================
// fp32 -> fp16 conversions
// =================================================================================
__device__ __forceinline__ uint32_t packh2(__half a, __half b) {
    return ((uint32_t)__half_as_ushort(b) << 16) | __half_as_ushort(a);
}

__global__ __launch_bounds__(256) void conv_half(
    const float4* __restrict__ src, uint2* __restrict__ dst, int n4)
{
    int i = blockIdx.x * 256 + threadIdx.x;
    if (i >= n4) return;
    float4 v = src[i];
    dst[i] = make_uint2(packh2(__float2half_rn(v.x), __float2half_rn(v.y)),
                        packh2(__float2half_rn(v.z), __float2half_rn(v.w)));
}

__global__ __launch_bounds__(256) void conv_half_split(
    const float4* __restrict__ src, uint2* __restrict__ hi, uint2* __restrict__ lo, int n4)
{
    int i = blockIdx.x * 256 + threadIdx.x;
    if (i >= n4) return;
    float4 v = src[i];
    __half h0 = __float2half_rn(v.x);
    __half h1 = __float2half_rn(v.y);
    __half h2 = __float2half_rn(v.z);
    __half h3 = __float2half_rn(v.w);
    hi[i] = make_uint2(packh2(h0, h1), packh2(h2, h3));
    __half l0 = __float2half_rn(v.x - __half2float(h0));
    __half l1 = __float2half_rn(v.y - __half2float(h1));
    __half l2 = __float2half_rn(v.z - __half2float(h2));
    __half l3 = __float2half_rn(v.w - __half2float(h3));
    lo[i] = make_uint2(packh2(l0, l1), packh2(l2, l3));
}

__global__ __launch_bounds__(256) void conv_wspk(
    const float* __restrict__ W, uint2* __restrict__ hi, uint2* __restrict__ lo)
{
    int idx = blockIdx.x * 256 + threadIdx.x;
    if (idx >= 300 * (KGEN / 4)) return;
    int row = idx / (KGEN / 4);
    int c4 = idx - row * (KGEN / 4);
    float v[4];
    #pragma unroll
    for (int q = 0; q < 4; q++) {
        int k = c4 * 4 + q;
        v[q] = (k < UDIM + FDIM) ? W[row * (UDIM + FDIM) + k] : 0.f;
    }
    __half h0 = __float2half_rn(v[0]), h1 = __float2half_rn(v[1]);
    __half h2 = __float2half_rn(v[2]), h3 = __float2half_rn(v[3]);
    hi[idx] = make_uint2(packh2(h0, h1), packh2(h2, h3));
    __half l0 = __float2half_rn(v[0] - __half2float(h0));
    __half l1 = __float2half_rn(v[1] - __half2float(h1));
    __half l2 = __float2half_rn(v[2] - __half2float(h2));
    __half l3 = __float2half_rn(v[3] - __half2float(h3));
    lo[idx] = make_uint2(packh2(l0, l1), packh2(l2, l3));
}

// =================================================================================
// Tensor-core GEMM: fp16 split-2, 2 passes, cstride/cmax (unchanged from R14).
// =================================================================================
#define BKT 64
#define TPAD 72
#define TILE_B (128 * TPAD * 2)
#define STAGE_B (3 * TILE_B)
#define SMG_BASE 1024
#define GEMM_SMEM (SMG_BASE + 2 * STAGE_B)

__device__ __forceinline__ uint32_t smem_u32(const void* p) {
    uint32_t a;
    asm("{ .reg .u64 t; cvta.to.shared.u64 t, %1; cvt.u32.u64 %0, t; }" : "=r"(a) : "l"(p));
    return a;
}

__device__ __forceinline__ void ldm_x4(uint32_t* r, uint32_t addr) {
    asm volatile("ldmatrix.sync.aligned.m8n8.x4.shared.b16 {%0,%1,%2,%3}, [%4];"
                 : "=r"(r[0]), "=r"(r[1]), "=r"(r[2]), "=r"(r[3]) : "r"(addr));
}

__device__ __forceinline__ void mma_fp16(float* d, const uint32_t* a, uint32_t b0, uint32_t b1) {
    asm volatile(
        "mma.sync.aligned.m16n8k16.row.col.f32.f16.f16.f32 "
        "{%0,%1,%2,%3}, {%4,%5,%6,%7}, {%8,%9}, {%0,%1,%2,%3};"
        : "+f"(d[0]), "+f"(d[1]), "+f"(d[2]), "+f"(d[3])
        : "r"(a[0]), "r"(a[1]), "r"(a[2]), "r"(a[3]), "r"(b0), "r"(b1));
}

__device__ __forceinline__ void cp_tile(
    const __half* __restrict__ src, int stride, int row0,
    int kbase, int kmax, uint32_t smDst, int tid)
{
    #pragma unroll
    for (int i = 0; i < 8; i++) {
        int idx = i * 256 + tid;
        int r = idx >> 4, c4 = idx & 15;
        int kg = kbase + c4 * 4;
        int sz = (kg < kmax) ? 8 : 0;
        int kgc = (kg < kmax) ? kg : 0;
        size_t off = (size_t)(row0 + r) * stride + kgc;
        uint32_t so = (uint32_t)(r * TPAD + c4 * 4) * 2;
        asm volatile("cp.async.ca.shared.global [%0], [%1], 8, %2;"
                     :: "r"(smDst + so), "l"(src + off), "r"(sz));
    }
}

__global__ __launch_bounds__(256, 2) void gemm_mma(
    const uint2* Ah0u, int K0, const uint2* Ah1u, int K1,
    const uint2* Whiu, const uint2* Wlou,
    const float* __restrict__ bias, float* __restrict__ C, int reverse,
    int cstride, int cmax)
{
    extern __shared__ char sm[];
    const __half* Ah0 = (const __half*)Ah0u;
    const __half* Ah1 = (const __half*)Ah1u;
    const __half* Whi = (const __half*)Whiu;
    const __half* Wlo = (const __half*)Wlou;

    const int tid  = threadIdx.x;
    const int warp = tid >> 5, lane = tid & 31;
    const int tb = blockIdx.x;
    const int n0 = blockIdx.y * 128;
    const int Ktot = K0 + K1;
    const int nkt = (Ktot + BKT - 1) / BKT;

    const int m0w = (warp >> 1) * 32;
    const int n0w = (warp & 1) * 64;
    const int laneRow  = lane & 15;
    const int laneHalf = lane >> 4;

    float* biass = (float*)sm;
    if (tid < 128) biass[tid] = bias[n0 + tid];

    const int arow0 = (reverse ? (T_STEPS - 1 - tb) : tb) * BATCH;
    const int crow0 = tb * BATCH;

    const uint32_t smBase = smem_u32(sm + SMG_BASE);

    float acc[2][8][4];
    #pragma unroll
    for (int mi = 0; mi < 2; mi++)
        #pragma unroll
        for (int nf = 0; nf < 8; nf++)
            #pragma unroll
            for (int q = 0; q < 4; q++) acc[mi][nf][q] = 0.f;

    auto issue_tile = [&](int kt) {
        const int k0 = kt * BKT;
        const uint32_t stg = smBase + (uint32_t)(kt & 1) * STAGE_B;
        if (k0 < K0)
            cp_tile(Ah0, K0, arow0, k0, K0, stg, tid);
        else
            cp_tile(Ah1, K1, arow0, k0 - K0, K1, stg, tid);
        cp_tile(Whi, Ktot, n0, k0, Ktot, stg + TILE_B, tid);
        cp_tile(Wlo, Ktot, n0, k0, Ktot, stg + 2 * TILE_B, tid);
    };

    issue_tile(0);
    asm volatile("cp.async.commit_group;" ::: "memory");

    for (int kt = 0; kt < nkt; kt++) {
        if (kt + 1 < nkt) issue_tile(kt + 1);
        asm volatile("cp.async.commit_group;" ::: "memory");
        asm volatile("cp.async.wait_group 1;" ::: "memory");
        __syncthreads();

        const uint32_t stg = smBase + (uint32_t)(kt & 1) * STAGE_B;
        const uint32_t sbA   = stg;
        const uint32_t sbBHI = stg + TILE_B;
        const uint32_t sbBLO = stg + 2 * TILE_B;

        #pragma unroll
        for (int ks = 0; ks < 4; ks++) {
            const uint32_t colb = (uint32_t)(ks * 16 + laneHalf * 8) * 2;

            uint32_t ah[2][4];
            #pragma unroll
            for (int mi = 0; mi < 2; mi++) {
                uint32_t ro = (uint32_t)(m0w + mi * 16 + laneRow) * (TPAD * 2) + colb;
                ldm_x4(ah[mi], sbA + ro);
            }
            uint32_t bh[8][2], bl[8][2];
            #pragma unroll
            for (int ni = 0; ni < 4; ni++) {
                uint32_t ro = (uint32_t)(n0w + ni * 16 + laneRow) * (TPAD * 2) + colb;
                uint32_t rb[4];
                ldm_x4(rb, sbBHI + ro);
                bh[2 * ni][0] = rb[0]; bh[2 * ni][1] = rb[2];
                bh[2 * ni + 1][0] = rb[1]; bh[2 * ni + 1][1] = rb[3];
                ldm_x4(rb, sbBLO + ro);
                bl[2 * ni][0] = rb[0]; bl[2 * ni][1] = rb[2];
                bl[2 * ni + 1][0] = rb[1]; bl[2 * ni + 1][1] = rb[3];
            }
            #pragma unroll
            for (int mi = 0; mi < 2; mi++)
                #pragma unroll
                for (int nf = 0; nf < 8; nf++)
                    mma_fp16(acc[mi][nf], ah[mi], bh[nf][0], bh[nf][1]);
            #pragma unroll
            for (int mi = 0; mi < 2; mi++)
                #pragma unroll
                for (int nf = 0; nf < 8; nf++)
                    mma_fp16(acc[mi][nf], ah[mi], bl[nf][0], bl[nf][1]);
        }
        __syncthreads();
    }

    float* stage = (float*)(sm + SMG_BASE);
    {
        const int g = lane >> 2, t4 = lane & 3;
        #pragma unroll
        for (int mi = 0; mi < 2; mi++)
            #pragma unroll
            for (int nf = 0; nf < 8; nf++) {
                int col = n0w + nf * 8 + 2 * t4;
                float* p0 = &stage[(m0w + mi * 16 + g) * 132 + col];
                float* p1 = &stage[(m0w + mi * 16 + g + 8) * 132 + col];
                p0[0] = acc[mi][nf][0]; p0[1] = acc[mi][nf][1];
                p1[0] = acc[mi][nf][2]; p1[1] = acc[mi][nf][3];
            }
    }
    __syncthreads();
    {
        const int col = tid & 127;
        if (n0 + col < cmax) {
            const float bcol = biass[col];
            #pragma unroll 4
            for (int it = 0; it < 64; it++) {
                int r = it * 2 + (tid >> 7);
                C[(size_t)(crow0 + r) * cstride + n0 + col] = stage[r * 132 + col] + bcol;
            }
        }
    }
}

// ---------------------------------------------------------------------------------
// Encoder bidirectional GRU scan — TWO batch rows per CTA (shared weight regs),
// 128 CTAs = 1 wave. Interleaved dual-row dot (4-chain ILP).
// ---------------------------------------------------------------------------------
__global__ __launch_bounds__(384, 1) void enc_scan(
    const float* __restrict__ Whh_f, const float* __restrict__ bhh_f,
    const float* __restrict__ Whh_b, const float* __restrict__ bhh_b,
    const float* __restrict__ enc_init)
{
    const int j = threadIdx.x;
    const int dir = blockIdx.x >> 6;
    const int bp  = blockIdx.x & 63;
    const int b0 = bp * 2;
    const float* Whh = dir ? Whh_b : Whh_f;
    const float* bhh = dir ? bhh_b : bhh_f;
    const float* xp = dir ? g_xpb : g_xpf;

    unsigned long long w2[64];
    {
        const unsigned long long* wr = (const unsigned long long*)(Whh + j * 128);
        #pragma unroll
        for (int k = 0; k < 64; k++) w2[k] = wr[k];
    }
    const float bh = bhh[j];

    __shared__ __align__(16) float h0_s[128];
    __shared__ __align__(16) float h1_s[128];
    __shared__ float hh0_s[384];
    __shared__ float hh1_s[384];
    if (j < 128) {
        float hi = enc_init[dir * 128 + j];
        h0_s[j] = hi; h1_s[j] = hi;
    }
    __syncthreads();

    const ulonglong2* h0v = (const ulonglong2*)h0_s;
    const ulonglong2* h1v = (const ulonglong2*)h1_s;

    const int jj = j & 127;
    const int myb = b0 + ((j >> 7) & 1);
    float pr = 0.f, pz = 0.f, pn = 0.f;
    if (j < 256) {
        const float* xr = xp + (size_t)myb * G3E;
        pr = xr[jj]; pz = xr[128 + jj]; pn = xr[256 + jj];
    }

    for (int t = 0; t < T_STEPS; t++) {
        float npr = 0.f, npz = 0.f, npn = 0.f;
        if (t + 1 < T_STEPS && j < 256) {
            const float* xr = xp + ((size_t)(t + 1) * BATCH + myb) * G3E;
            npr = xr[jj]; npz = xr[128 + jj]; npn = xr[256 + jj];
        }

        unsigned long long c00 = 0ull, c01 = 0ull, c10 = 0ull, c11 = 0ull;
        #pragma unroll
        for (int kk = 0; kk < 32; kk++) {
            ulonglong2 a0 = h0v[kk];
            ulonglong2 a1 = h1v[kk];
            FMA2(c00, w2[2 * kk + 0], a0.x);
            FMA2(c01, w2[2 * kk + 1], a0.y);
            FMA2(c10, w2[2 * kk + 0], a1.x);
            FMA2(c11, w2[2 * kk + 1], a1.y);
        }
        hh0_s[j] = bh + (sum2(c00) + sum2(c01));
        hh1_s[j] = bh + (sum2(c10) + sum2(c11));
        __syncthreads();

        if (j < 256) {
            const float* hhs = (j < 128) ? hh0_s : hh1_s;
            float* hs = (j < 128) ? h0_s : h1_s;
            float r = sigmf(pr + hhs[jj]);
            float z = sigmf(pz + hhs[128 + jj]);
            float n = tanhf_fast(pn + r * hhs[256 + jj]);
            float h = (1.f - z) * n + z * hs[jj];
            hs[jj] = h;
            float gc = fminf(fmaxf(h, -CLIPV), CLIPV);
            int tt = dir ? (T_STEPS - 1 - t) : t;
            g_g[((size_t)tt * BATCH + myb) * (2 * EDIM) + dir * EDIM + jj] = gc;
        }
        __syncthreads();
        pr = npr; pz = npz; pn = npn;
    }
}

// ---------------------------------------------------------------------------------
// Controller scan — PURE GRU (R14 version, unchanged).
// ---------------------------------------------------------------------------------
__global__ __launch_bounds__(384, 1) void ctrl_scan(
    const float* __restrict__ Whh, const float* __restrict__ bhh,
    const float* __restrict__ cinit)
{
    const int j = threadIdx.x;
    const int b = blockIdx.x;

    unsigned long long w2[64];
    {
        const unsigned long long* wr = (const unsigned long long*)(Whh + j * 128);
        #pragma unroll
        for (int k = 0; k < 64; k++) w2[k] = wr[k];
    }
    const float bh = bhh[j];

    __shared__ __align__(16) float h_s[128];
    __shared__ float hh_s[384];
    if (j < 128) h_s[j] = cinit[j];
    __syncthreads();

    const ulonglong2* h2v = (const ulonglong2*)h_s;
    __half* hf = (__half*)g_hfu;

    float pr = 0.f, pz = 0.f, pn = 0.f;
    if (j < 128) {
        const float* cpr = g_cp + (size_t)b * G3E;
        pr = cpr[j]; pz = cpr[128 + j]; pn = cpr[256 + j];
    }

    for (int t = 0; t < T_STEPS; t++) {
        size_t row = (size_t)t * BATCH + b;
        float npr = 0.f, npz = 0.f, npn = 0.f;
        if (t + 1 < T_STEPS && j < 128) {
            const float* cpr = g_cp + (row + BATCH) * G3E;
            npr = cpr[j]; npz = cpr[128 + j]; npn = cpr[256 + j];
        }

        unsigned long long c0 = 0ull, c1 = 0ull, c2 = 0ull, c3 = 0ull;
        #pragma unroll
        for (int kk = 0; kk < 16; kk++) {
            ulonglong2 ha = h2v[2 * kk];
            ulonglong2 hb = h2v[2 * kk + 1];
            FMA2(c0, w2[4 * kk + 0], ha.x);
            FMA2(c1, w2[4 * kk + 1], ha.y);
            FMA2(c2, w2[4 * kk + 2], hb.x);
            FMA2(c3, w2[4 * kk + 3], hb.y);
        }
        hh_s[j] = bh + ((sum2(c0) + sum2(c1)) + (sum2(c2) + sum2(c3)));
        __syncthreads();

        if (j < 128) {
            float r = sigmf(pr + hh_s[j]);
            float z = sigmf(pz + hh_s[128 + j]);
            float n = tanhf_fast(pn + r * hh_s[256 + j]);
            float h = (1.f - z) * n + z * h_s[j];
            h = fminf(fmaxf(h, -CLIPV), CLIPV);
            h_s[j] = h;
            hf[row * CDIM + j] = __float2half_rn(h);
        }
        __syncthreads();
        pr = npr; pz = npz; pn = npn;
    }
}

// ---------------------------------------------------------------------------------
// gen kernel (unchanged from R14)
// ---------------------------------------------------------------------------------
__global__ __launch_bounds__(256) void gen_kernel(
    const float* __restrict__ mlv, const float* __restrict__ eps,
    const float* __restrict__ factors,
    const float* __restrict__ bmu, const float* __restrict__ blv)
{
    int idx = blockIdx.x * 256 + threadIdx.x;
    if (idx >= NROWS * KGEN) return;
    int row = idx / KGEN;
    int j = idx - row * KGEN;
    float v = 0.f;
    if (j < UDIM) {
        float mu = mlv[(size_t)row * 128 + j] + bmu[j];
        float lv = mlv[(size_t)row * 128 + UDIM + j] + blv[j];
        v = mu + __expf(0.5f * lv) * eps[(size_t)row * UDIM + j];
    } else if (j < UDIM + FDIM) {
        v = factors[(size_t)row * FDIM + (j - UDIM)];
    }
    ((__half*)g_genh)[idx] = __float2half_rn(v);
}

// ---------------------------------------------------------------------------------
// calcium kernel (unchanged from R14)
// ---------------------------------------------------------------------------------
__global__ __launch_bounds__(128) void calcium_kernel(
    const float* __restrict__ logits, const float* __restrict__ bspk,
    const float* __restrict__ gain_p, const float* __restrict__ biasp_p,
    const float* __restrict__ ltau_p, float* __restrict__ out)
{
    int idx = blockIdx.x * 128 + threadIdx.x;
    if (idx >= BATCH * NIN) return;
    const int n = idx % NIN;
    const float bsp = bspk[n];
    const float gain = gain_p[0];
    const float biasp = biasp_p[0];
    const float decay = 1.f - expf(-ltau_p[0]);
    float cal = 0.f;
    const size_t stride = (size_t)BATCH * NIN;
    const float* lp = logits + idx;
    float* op = out + idx;
    for (int t = 0; t < T_STEPS; t += 4) {
        float l0 = lp[(size_t)(t + 0) * stride];
        float l1 = lp[(size_t)(t + 1) * stride];
        float l2 = lp[(size_t)(t + 2) * stride];
        float l3 = lp[(size_t)(t + 3) * stride];
        float s;
        s = fmaxf(__expf(l0 + bsp) - 1.f, 0.f); cal = cal * decay + gain * s + biasp;
        op[(size_t)(t + 0) * stride] = cal;
        s = fmaxf(__expf(l1 + bsp) - 1.f, 0.f); cal = cal * decay + gain * s + biasp;
        op[(size_t)(t + 1) * stride] = cal;
        s = fmaxf(__expf(l2 + bsp) - 1.f, 0.f); cal = cal * decay + gain * s + biasp;
        op[(size_t)(t + 2) * stride] = cal;
        s = fmaxf(__expf(l3 + bsp) - 1.f, 0.f); cal = cal * decay + gain * s + biasp;
        op[(size_t)(t + 3) * stride] = cal;
    }
}

// ---------------------------------------------------------------------------------
extern "C" void kernel_launch(void* const* d_in, const int* in_sizes, int n_in,
                              void* d_out, int out_size)
{
    (void)in_sizes; (void)n_in; (void)out_size;
    const float* x       = (const float*)d_in[0];
    const float* factors = (const float*)d_in[1];
    const float* eps     = (const float*)d_in[2];
    const float* eWihf   = (const float*)d_in[3];
    const float* eWhhf   = (const float*)d_in[4];
    const float* ebihf   = (const float*)d_in[5];
    const float* ebhhf   = (const float*)d_in[6];
    const float* eWihb   = (const float*)d_in[7];
    const float* eWhhb   = (const float*)d_in[8];
    const float* ebihb   = (const float*)d_in[9];
    const float* ebhhb   = (const float*)d_in[10];
    const float* einit   = (const float*)d_in[11];
    const float* cWih    = (const float*)d_in[12];
    const float* cWhh    = (const float*)d_in[13];
    const float* cbih    = (const float*)d_in[14];
    const float* cbhh    = (const float*)d_in[15];
    const float* cinit   = (const float*)d_in[16];
    const float* Wmu     = (const float*)d_in[17];
    const float* bmu     = (const float*)d_in[18];
    const float* Wlv     = (const float*)d_in[19];
    const float* blv     = (const float*)d_in[20];
    const float* Wspk    = (const float*)d_in[21];
    const float* bspk    = (const float*)d_in[22];
    const float* gain    = (const float*)d_in[23];
    const float* bp      = (const float*)d_in[24];
    const float* ltau    = (const float*)d_in[25];
    float* out = (float*)d_out;

    float *xpf, *xpb, *gg, *cp, *zero;
    cudaGetSymbolAddress((void**)&xpf, g_xpf);
    cudaGetSymbolAddress((void**)&xpb, g_xpb);
    cudaGetSymbolAddress((void**)&gg,  g_g);
    cudaGetSymbolAddress((void**)&cp,  g_cp);
    cudaGetSymbolAddress((void**)&zero, g_zero);

    uint2 *xh, *gh, *wfh, *wfl, *wbh, *wbl, *wch, *wcl, *wmh, *wml, *wsh, *wsl, *hfu, *genh;
    cudaGetSymbolAddress((void**)&xh, g_xh);
    cudaGetSymbolAddress((void**)&gh, g_gh);
    cudaGetSymbolAddress((void**)&wfh, g_wfh); cudaGetSymbolAddress((void**)&wfl, g_wfl);
    cudaGetSymbolAddress((void**)&wbh, g_wbh); cudaGetSymbolAddress((void**)&wbl, g_wbl);
    cudaGetSymbolAddress((void**)&wch, g_wch); cudaGetSymbolAddress((void**)&wcl, g_wcl);
    cudaGetSymbolAddress((void**)&wmh, g_wmh); cudaGetSymbolAddress((void**)&wml, g_wml);
    cudaGetSymbolAddress((void**)&wsh, g_wsh); cudaGetSymbolAddress((void**)&wsl, g_wsl);
    cudaGetSymbolAddress((void**)&hfu, g_hfu);
    cudaGetSymbolAddress((void**)&genh, g_genh);

    cudaFuncSetAttribute(gemm_mma, cudaFuncAttributeMaxDynamicSharedMemorySize, GEMM_SMEM);

    dim3 gemm_grid(T_STEPS, G3E / 128);

    // launches 1-5 (so enc_scan is #6, landing in the ncu capture slot)
    conv_half<<<(XN4 + 255) / 256, 256>>>((const float4*)x, xh, XN4);
    conv_half_split<<<(WFN4 + 255) / 256, 256>>>((const float4*)eWihf, wfh, wfl, WFN4);
    conv_half_split<<<(WFN4 + 255) / 256, 256>>>((const float4*)eWihb, wbh, wbl, WFN4);
    gemm_mma<<<gemm_grid, 256, GEMM_SMEM>>>(xh, NIN, nullptr, 0, wfh, wfl, ebihf, xpf, 0, G3E, G3E);
    gemm_mma<<<gemm_grid, 256, GEMM_SMEM>>>(xh, NIN, nullptr, 0, wbh, wbl, ebihb, xpb, 1, G3E, G3E);

    // #6: bidirectional encoder scan (128 CTAs, 2 rows each, 1 wave)  [captured]
    enc_scan<<<128, 384>>>(eWhhf, ebhhf, eWhhb, ebhhb, einit);

    // cp = [g, x] @ ctrl_Wih^T + b
    conv_half_split<<<(WCN4 + 255) / 256, 256>>>((const float4*)cWih, wch, wcl, WCN4);
    conv_half<<<(GN4 + 255) / 256, 256>>>((const float4*)gg, gh, GN4);
    gemm_mma<<<gemm_grid, 256, GEMM_SMEM>>>(gh, 2 * EDIM, xh, NIN, wch, wcl, cbih, cp, 0, G3E, G3E);

    // controller pure-GRU scan -> h fp16
    ctrl_scan<<<128, 384>>>(cWhh, cbhh, cinit);

    // downstream batched kernels
    conv_half_split<<<(WMN4 + 255) / 256, 256>>>((const float4*)Wmu, wmh, wml, WMN4);
    conv_half_split<<<(WMN4 + 255) / 256, 256>>>((const float4*)Wlv, wmh + WMN4, wml + WMN4, WMN4);
    conv_wspk<<<(300 * (KGEN / 4) + 255) / 256, 256>>>(Wspk, wsh, wsl);

    gemm_mma<<<dim3(T_STEPS, 1), 256, GEMM_SMEM>>>(hfu, CDIM, nullptr, 0,
                                                   wmh, wml, zero, xpf, 0, 128, 128);
    gen_kernel<<<(NROWS * KGEN + 255) / 256, 256>>>(xpf, eps, factors, bmu, blv);
    gemm_mma<<<dim3(T_STEPS, 3), 256, GEMM_SMEM>>>(genh, KGEN, nullptr, 0,
                                                   wsh, wsl, zero, xpb, 0, NIN, NIN);
    calcium_kernel<<<(BATCH * NIN + 127) / 128, 128>>>(xpb, bspk, gain, bp, ltau, out);
}